// round 13
// baseline (speedup 1.0000x reference)
#include <cuda_runtime.h>
#include <cuda_bf16.h>
#include <cstdint>
#include <math.h>

// ---------------- static scratch (allocation-free rule) ----------------
__device__ float g_h   [2000*512];
__device__ float g_xA1 [4000*256];
__device__ float g_xB1 [4000*256];
__device__ float g_xA2 [4000*256];
__device__ float g_xB2 [4000*256];
__device__ float g_axu [4000*512];
__device__ float g_tc1 [4000*256];
__device__ float g_tc2 [4000*256];
__device__ float g_s0  [2u*2000*2000];
__device__ float g_T1  [2000*256];
__device__ float g_Ssym[256*256];
__device__ float g_bcat[512];
__device__ float g_cs  [2*4096];
__device__ float g_u   [2*2048];
__device__ float g_v   [2*2048];
__device__ float g_Rf  [2*2048];
__device__ float g_Cf  [2*2048];
__device__ float g_sq  [4*2048];
__device__ float g_gmax[2];
__device__ float g_part[5u*4000*256];                 // split-K partials
__device__ __nv_bfloat16 g_Abf[2ull*2*4096*4096];     // A 2-term bf16 (both graphs, padded)
__device__ __nv_bfloat16 g_Bbf[2ull*256*4096];        // ax^T 2-term bf16 (padded)
__device__ __nv_bfloat16 g_ntA[3u*2048*256];          // NT operand A 3-term / emb 3-term
__device__ __nv_bfloat16 g_ntB[3u*2048*256];          // NT operand B 3-term
__device__ __nv_bfloat16 g_s0bf[2ull*2*2048*2048];    // s0 2-term, normal + transposed
__device__ __nv_bfloat16 g_cgB [2u*256*2048];         // cross-graph B 2-term transposed
__device__ __nv_bfloat16 g_Xbf [3u*4096*256];         // x 3-term / h 3-term (padded rows)
__device__ __nv_bfloat16 g_Bw  [3u*512*256];          // [wa|wu]^T 3-term
__device__ __nv_bfloat16 g_w1n [3u*512*128];
__device__ __nv_bfloat16 g_w1e [3u*512*128];
__device__ __nv_bfloat16 g_w2n [3u*256*512];
__device__ __nv_bfloat16 g_w2e [3u*256*512];

// ---------------- reductions ----------------
__device__ __forceinline__ float warpReduceSum(float v){
#pragma unroll
    for (int o=16;o;o>>=1) v += __shfl_xor_sync(0xffffffffu, v, o);
    return v;
}
__device__ __forceinline__ float warpReduceMax(float v){
#pragma unroll
    for (int o=16;o;o>>=1) v = fmaxf(v, __shfl_xor_sync(0xffffffffu, v, o));
    return v;
}
__device__ __forceinline__ float blockReduceSum256(float v){
    __shared__ float sm[8];
    float w = warpReduceSum(v);
    int wi = threadIdx.x>>5, ln = threadIdx.x&31;
    if (ln==0) sm[wi] = w;
    __syncthreads();
    if (wi==0){ float t = (ln<8)?sm[ln]:0.f; t = warpReduceSum(t); if (ln==0) sm[0]=t; }
    __syncthreads();
    float r = sm[0];
    __syncthreads();
    return r;
}
__device__ __forceinline__ float blockReduceMax256(float v){
    __shared__ float sm[8];
    float w = warpReduceMax(v);
    int wi = threadIdx.x>>5, ln = threadIdx.x&31;
    if (ln==0) sm[wi] = w;
    __syncthreads();
    if (wi==0){ float t = (ln<8)?sm[ln]:-1e30f; t = warpReduceMax(t); if (ln==0) sm[0]=t; }
    __syncthreads();
    float r = sm[0];
    __syncthreads();
    return r;
}

// ================= mma.sync primitive =================
__device__ __forceinline__ void mma16816(float* d, const uint32_t* a, uint32_t b0, uint32_t b1){
    asm volatile(
        "mma.sync.aligned.m16n8k16.row.col.f32.bf16.bf16.f32 "
        "{%0,%1,%2,%3}, {%4,%5,%6,%7}, {%8,%9}, {%0,%1,%2,%3};"
        : "+f"(d[0]), "+f"(d[1]), "+f"(d[2]), "+f"(d[3])
        : "r"(a[0]), "r"(a[1]), "r"(a[2]), "r"(a[3]), "r"(b0), "r"(b1));
}

#define SM_ROW 40                 // 32 k + 8 pad bf16 (80 B rows, 16B-aligned)
#define TERM_SZ (128*SM_ROW)

// ======== big GEMM: 2-term/3-product (positive operands), unchanged ========
#define BUF_SZ  (4*TERM_SZ)
#define MMA_SMEM (2*BUF_SZ*2)     // 81920 bytes -> 2 CTAs/SM

__global__ void __launch_bounds__(256,2) mma_big_k(
    const __nv_bfloat16* __restrict__ Abf,
    const __nv_bfloat16* __restrict__ Bbf,
    float* __restrict__ part)
{
    extern __shared__ __nv_bfloat16 sm[];
    uint32_t smb;
    asm("{ .reg .u64 t; cvta.to.shared.u64 t, %1; cvt.u32.u64 %0, t; }" : "=r"(smb) : "l"(sm));
    const int tid = threadIdx.x;
    const int lane = tid & 31, wid = tid >> 5;
    const int grp = lane >> 2, qid = lane & 3;
    const int warp_m = (wid & 3) * 32;
    const int warp_n = (wid >> 2) * 64;
    const int n0 = blockIdx.x * 128;
    const int m0 = blockIdx.y * 128;
    const int kbeg = blockIdx.z * 1024;

    const int r0 = tid >> 2,         c8 = (tid & 3) << 3;
    const int r1 = (256 + tid) >> 2;

    float acc[2][8][4];
#pragma unroll
    for (int i=0;i<2;++i)
#pragma unroll
        for (int j=0;j<8;++j)
#pragma unroll
            for (int q=0;q<4;++q) acc[i][j][q] = 0.f;

    auto prefetch = [&](int iter, int buf){
        int k0 = kbeg + iter*32;
        uint32_t base = smb + (uint32_t)(buf*BUF_SZ)*2;
#pragma unroll
        for (int t=0; t<2; ++t){
            const __nv_bfloat16* ga0 = Abf + (size_t)t*16777216ull + (size_t)(m0+r0)*4096 + k0 + c8;
            const __nv_bfloat16* ga1 = Abf + (size_t)t*16777216ull + (size_t)(m0+r1)*4096 + k0 + c8;
            uint32_t da0 = base + (uint32_t)(t*TERM_SZ + r0*SM_ROW + c8)*2;
            uint32_t da1 = base + (uint32_t)(t*TERM_SZ + r1*SM_ROW + c8)*2;
            asm volatile("cp.async.cg.shared.global [%0], [%1], 16;" :: "r"(da0), "l"(ga0));
            asm volatile("cp.async.cg.shared.global [%0], [%1], 16;" :: "r"(da1), "l"(ga1));
            const __nv_bfloat16* gb0 = Bbf + (size_t)t*1048576ull + (size_t)(n0+r0)*4096 + k0 + c8;
            const __nv_bfloat16* gb1 = Bbf + (size_t)t*1048576ull + (size_t)(n0+r1)*4096 + k0 + c8;
            uint32_t db0 = base + (uint32_t)((2+t)*TERM_SZ + r0*SM_ROW + c8)*2;
            uint32_t db1 = base + (uint32_t)((2+t)*TERM_SZ + r1*SM_ROW + c8)*2;
            asm volatile("cp.async.cg.shared.global [%0], [%1], 16;" :: "r"(db0), "l"(gb0));
            asm volatile("cp.async.cg.shared.global [%0], [%1], 16;" :: "r"(db1), "l"(gb1));
        }
        asm volatile("cp.async.commit_group;");
    };

    prefetch(0, 0);

    for (int it = 0; it < 32; ++it){
        if (it + 1 < 32){
            prefetch(it+1, (it+1)&1);
            asm volatile("cp.async.wait_group 1;");
        } else {
            asm volatile("cp.async.wait_group 0;");
        }
        __syncthreads();
        const __nv_bfloat16* As = sm + (it&1)*BUF_SZ;
        const __nv_bfloat16* Bs = As + 2*TERM_SZ;
#pragma unroll
        for (int kk=0; kk<32; kk+=16){
            uint32_t afr[2][2][4];
#pragma unroll
            for (int t=0; t<2; ++t)
#pragma unroll
                for (int mf=0; mf<2; ++mf){
                    const __nv_bfloat16* ap = As + t*TERM_SZ + (warp_m + mf*16 + grp)*SM_ROW + kk + qid*2;
                    afr[t][mf][0] = *(const uint32_t*)(ap);
                    afr[t][mf][1] = *(const uint32_t*)(ap + 8*SM_ROW);
                    afr[t][mf][2] = *(const uint32_t*)(ap + 8);
                    afr[t][mf][3] = *(const uint32_t*)(ap + 8*SM_ROW + 8);
                }
#pragma unroll
            for (int nf=0; nf<8; ++nf){
                const __nv_bfloat16* bb = Bs + (warp_n + nf*8 + grp)*SM_ROW + kk + qid*2;
                uint32_t b0[2], b1[2];
#pragma unroll
                for (int t=0; t<2; ++t){
                    b0[t] = *(const uint32_t*)(bb + t*TERM_SZ);
                    b1[t] = *(const uint32_t*)(bb + t*TERM_SZ + 8);
                }
                mma16816(acc[0][nf], afr[0][0], b0[0], b1[0]);
                mma16816(acc[1][nf], afr[0][1], b0[0], b1[0]);
                mma16816(acc[0][nf], afr[0][0], b0[1], b1[1]);
                mma16816(acc[1][nf], afr[0][1], b0[1], b1[1]);
                mma16816(acc[0][nf], afr[1][0], b0[0], b1[0]);
                mma16816(acc[1][nf], afr[1][1], b0[0], b1[0]);
            }
        }
        __syncthreads();
    }

    float* pb = part + (size_t)blockIdx.z * (4000*256);
#pragma unroll
    for (int mf=0; mf<2; ++mf){
        int gm0 = m0 + warp_m + mf*16 + grp;
        int gm1 = gm0 + 8;
#pragma unroll
        for (int nf=0; nf<8; ++nf){
            int gn = n0 + warp_n + nf*8 + qid*2;
            if (gm0 < 4000){
                float2 v0 = make_float2(acc[mf][nf][0], acc[mf][nf][1]);
                *(float2*)(pb + (size_t)gm0*256 + gn) = v0;
            }
            if (gm1 < 4000){
                float2 v1 = make_float2(acc[mf][nf][2], acc[mf][nf][3]);
                *(float2*)(pb + (size_t)gm1*256 + gn) = v1;
            }
        }
    }
}

// ======== NT GEMM 2000x2000x256: 3-term/6-product (unchanged) ========
#define NT_BUF  (6*TERM_SZ)
#define NT_SMEM (NT_BUF*2)

template<int ACT>
__global__ void __launch_bounds__(256,2) mma_nt_k(
    const __nv_bfloat16* __restrict__ A,
    const __nv_bfloat16* __restrict__ B,
    float* __restrict__ out,
    const float* __restrict__ xsq, const float* __restrict__ ysq,
    float* __restrict__ gmax)
{
    extern __shared__ __nv_bfloat16 sm[];
    uint32_t smb;
    asm("{ .reg .u64 t; cvta.to.shared.u64 t, %1; cvt.u32.u64 %0, t; }" : "=r"(smb) : "l"(sm));
    const int tid = threadIdx.x;
    const int lane = tid & 31, wid = tid >> 5;
    const int grp = lane >> 2, qid = lane & 3;
    const int warp_m = (wid & 3) * 32;
    const int warp_n = (wid >> 2) * 64;
    const int n0 = blockIdx.x * 128;
    const int m0 = blockIdx.y * 128;

    const int r0 = tid >> 2,         c8 = (tid & 3) << 3;
    const int r1 = (256 + tid) >> 2;

    float acc[2][8][4];
#pragma unroll
    for (int i=0;i<2;++i)
#pragma unroll
        for (int j=0;j<8;++j)
#pragma unroll
            for (int q=0;q<4;++q) acc[i][j][q] = 0.f;

    const int pA[6] = {0,0,1,1,0,2};
    const int pB[6] = {0,1,0,1,2,0};

    for (int it = 0; it < 8; ++it){
        int k0 = it*32;
#pragma unroll
        for (int t=0; t<3; ++t){
            const __nv_bfloat16* ga0 = A + (size_t)t*524288ull + (size_t)(m0+r0)*256 + k0 + c8;
            const __nv_bfloat16* ga1 = A + (size_t)t*524288ull + (size_t)(m0+r1)*256 + k0 + c8;
            uint32_t da0 = smb + (uint32_t)(t*TERM_SZ + r0*SM_ROW + c8)*2;
            uint32_t da1 = smb + (uint32_t)(t*TERM_SZ + r1*SM_ROW + c8)*2;
            asm volatile("cp.async.cg.shared.global [%0], [%1], 16;" :: "r"(da0), "l"(ga0));
            asm volatile("cp.async.cg.shared.global [%0], [%1], 16;" :: "r"(da1), "l"(ga1));
            const __nv_bfloat16* gb0 = B + (size_t)t*524288ull + (size_t)(n0+r0)*256 + k0 + c8;
            const __nv_bfloat16* gb1 = B + (size_t)t*524288ull + (size_t)(n0+r1)*256 + k0 + c8;
            uint32_t db0 = smb + (uint32_t)((3+t)*TERM_SZ + r0*SM_ROW + c8)*2;
            uint32_t db1 = smb + (uint32_t)((3+t)*TERM_SZ + r1*SM_ROW + c8)*2;
            asm volatile("cp.async.cg.shared.global [%0], [%1], 16;" :: "r"(db0), "l"(gb0));
            asm volatile("cp.async.cg.shared.global [%0], [%1], 16;" :: "r"(db1), "l"(gb1));
        }
        asm volatile("cp.async.commit_group;");
        asm volatile("cp.async.wait_group 0;");
        __syncthreads();
        const __nv_bfloat16* As = sm;
        const __nv_bfloat16* Bs = sm + 3*TERM_SZ;
#pragma unroll
        for (int kk=0; kk<32; kk+=16){
            uint32_t afr[3][2][4];
#pragma unroll
            for (int t=0; t<3; ++t)
#pragma unroll
                for (int mf=0; mf<2; ++mf){
                    const __nv_bfloat16* ap = As + t*TERM_SZ + (warp_m + mf*16 + grp)*SM_ROW + kk + qid*2;
                    afr[t][mf][0] = *(const uint32_t*)(ap);
                    afr[t][mf][1] = *(const uint32_t*)(ap + 8*SM_ROW);
                    afr[t][mf][2] = *(const uint32_t*)(ap + 8);
                    afr[t][mf][3] = *(const uint32_t*)(ap + 8*SM_ROW + 8);
                }
#pragma unroll
            for (int nf=0; nf<8; ++nf){
                const __nv_bfloat16* bb = Bs + (warp_n + nf*8 + grp)*SM_ROW + kk + qid*2;
                uint32_t b0[3], b1[3];
#pragma unroll
                for (int t=0; t<3; ++t){
                    b0[t] = *(const uint32_t*)(bb + t*TERM_SZ);
                    b1[t] = *(const uint32_t*)(bb + t*TERM_SZ + 8);
                }
#pragma unroll
                for (int p=0; p<6; ++p){
                    mma16816(acc[0][nf], afr[pA[p]][0], b0[pB[p]], b1[pB[p]]);
                    mma16816(acc[1][nf], afr[pA[p]][1], b0[pB[p]], b1[pB[p]]);
                }
            }
        }
        __syncthreads();
    }

    float dmax = 0.f;
#pragma unroll
    for (int mf=0; mf<2; ++mf){
#pragma unroll
        for (int q2=0; q2<2; ++q2){
            int gm = m0 + warp_m + mf*16 + grp + q2*8;
            if (gm < 2000){
#pragma unroll
                for (int nf=0; nf<8; ++nf){
#pragma unroll
                    for (int e=0; e<2; ++e){
                        int gn = n0 + warp_n + nf*8 + qid*2 + e;
                        if (gn < 2000){
                            float v = acc[mf][nf][q2*2+e];
                            if (ACT==3){
                                v = sqrtf(fmaxf(xsq[gm]+ysq[gn]-2.f*v, 0.f));
                                dmax = fmaxf(dmax, v);
                            }
                            out[(size_t)gm*2000 + gn] = v;
                        }
                    }
                }
            }
        }
    }
    if (ACT==3){
        __shared__ float red[256];
        red[tid] = dmax; __syncthreads();
        for (int s=128;s;s>>=1){ if (tid<s) red[tid]=fmaxf(red[tid],red[tid+s]); __syncthreads(); }
        if (tid==0) atomicMax((int*)gmax, __float_as_int(red[0]));
    }
}

// ======== unified AB^T GEMM: out[M, NB] = A[M,LDK] @ B[NB,LDK]^T, 3-term/6-product ====
// A: [3][APAD][LDK] bf16; B: [3][NB][LDK] bf16. ACT: 0 raw, 1 bias+relu.
template<int KITER, int LDK, int APAD, int NB, int ACT>
__global__ void __launch_bounds__(256,2) mma_ab_k(
    const __nv_bfloat16* __restrict__ A,
    const __nv_bfloat16* __restrict__ B,
    const float* __restrict__ bias,
    float* __restrict__ out, int M, int ldo)
{
    extern __shared__ __nv_bfloat16 sm[];
    uint32_t smb;
    asm("{ .reg .u64 t; cvta.to.shared.u64 t, %1; cvt.u32.u64 %0, t; }" : "=r"(smb) : "l"(sm));
    const int tid = threadIdx.x;
    const int lane = tid & 31, wid = tid >> 5;
    const int grp = lane >> 2, qid = lane & 3;
    const int warp_m = (wid & 3) * 32;
    const int warp_n = (wid >> 2) * 64;
    const int n0 = blockIdx.x * 128;
    const int m0 = blockIdx.y * 128;

    const int r0 = tid >> 2,         c8 = (tid & 3) << 3;
    const int r1 = (256 + tid) >> 2;

    float acc[2][8][4];
#pragma unroll
    for (int i=0;i<2;++i)
#pragma unroll
        for (int j=0;j<8;++j)
#pragma unroll
            for (int q=0;q<4;++q) acc[i][j][q] = 0.f;

    const int pA[6] = {0,0,1,1,0,2};
    const int pB[6] = {0,1,0,1,2,0};

    for (int it = 0; it < KITER; ++it){
        int k0 = it*32;
#pragma unroll
        for (int t=0; t<3; ++t){
            const __nv_bfloat16* ga0 = A + (size_t)t*((size_t)APAD*LDK) + (size_t)(m0+r0)*LDK + k0 + c8;
            const __nv_bfloat16* ga1 = A + (size_t)t*((size_t)APAD*LDK) + (size_t)(m0+r1)*LDK + k0 + c8;
            uint32_t da0 = smb + (uint32_t)(t*TERM_SZ + r0*SM_ROW + c8)*2;
            uint32_t da1 = smb + (uint32_t)(t*TERM_SZ + r1*SM_ROW + c8)*2;
            asm volatile("cp.async.cg.shared.global [%0], [%1], 16;" :: "r"(da0), "l"(ga0));
            asm volatile("cp.async.cg.shared.global [%0], [%1], 16;" :: "r"(da1), "l"(ga1));
            const __nv_bfloat16* gb0 = B + (size_t)t*((size_t)NB*LDK) + (size_t)(n0+r0)*LDK + k0 + c8;
            const __nv_bfloat16* gb1 = B + (size_t)t*((size_t)NB*LDK) + (size_t)(n0+r1)*LDK + k0 + c8;
            uint32_t db0 = smb + (uint32_t)((3+t)*TERM_SZ + r0*SM_ROW + c8)*2;
            uint32_t db1 = smb + (uint32_t)((3+t)*TERM_SZ + r1*SM_ROW + c8)*2;
            asm volatile("cp.async.cg.shared.global [%0], [%1], 16;" :: "r"(db0), "l"(gb0));
            asm volatile("cp.async.cg.shared.global [%0], [%1], 16;" :: "r"(db1), "l"(gb1));
        }
        asm volatile("cp.async.commit_group;");
        asm volatile("cp.async.wait_group 0;");
        __syncthreads();
        const __nv_bfloat16* As = sm;
        const __nv_bfloat16* Bs = sm + 3*TERM_SZ;
#pragma unroll
        for (int kk=0; kk<32; kk+=16){
            uint32_t afr[3][2][4];
#pragma unroll
            for (int t=0; t<3; ++t)
#pragma unroll
                for (int mf=0; mf<2; ++mf){
                    const __nv_bfloat16* ap = As + t*TERM_SZ + (warp_m + mf*16 + grp)*SM_ROW + kk + qid*2;
                    afr[t][mf][0] = *(const uint32_t*)(ap);
                    afr[t][mf][1] = *(const uint32_t*)(ap + 8*SM_ROW);
                    afr[t][mf][2] = *(const uint32_t*)(ap + 8);
                    afr[t][mf][3] = *(const uint32_t*)(ap + 8*SM_ROW + 8);
                }
#pragma unroll
            for (int nf=0; nf<8; ++nf){
                const __nv_bfloat16* bb = Bs + (warp_n + nf*8 + grp)*SM_ROW + kk + qid*2;
                uint32_t b0[3], b1[3];
#pragma unroll
                for (int t=0; t<3; ++t){
                    b0[t] = *(const uint32_t*)(bb + t*TERM_SZ);
                    b1[t] = *(const uint32_t*)(bb + t*TERM_SZ + 8);
                }
#pragma unroll
                for (int p=0; p<6; ++p){
                    mma16816(acc[0][nf], afr[pA[p]][0], b0[pB[p]], b1[pB[p]]);
                    mma16816(acc[1][nf], afr[pA[p]][1], b0[pB[p]], b1[pB[p]]);
                }
            }
        }
        __syncthreads();
    }

#pragma unroll
    for (int mf=0; mf<2; ++mf){
#pragma unroll
        for (int q2=0; q2<2; ++q2){
            int gm = m0 + warp_m + mf*16 + grp + q2*8;
            if (gm < M){
#pragma unroll
                for (int nf=0; nf<8; ++nf){
                    int gn = n0 + warp_n + nf*8 + qid*2;
                    float v0 = acc[mf][nf][q2*2+0];
                    float v1 = acc[mf][nf][q2*2+1];
                    if (ACT==1){
                        v0 = fmaxf(v0 + bias[gn],   0.f);
                        v1 = fmaxf(v1 + bias[gn+1], 0.f);
                    }
                    *(float2*)(out + (size_t)gm*ldo + gn) = make_float2(v0, v1);
                }
            }
        }
    }
}

// ======== cross-graph GEMM (unchanged) ========
#define CG_BUF  (4*TERM_SZ)
#define CG_SMEM (CG_BUF*2)

__global__ void __launch_bounds__(256,2) mma_cg_k(
    const __nv_bfloat16* __restrict__ A,
    const __nv_bfloat16* __restrict__ B,
    float* __restrict__ part)
{
    extern __shared__ __nv_bfloat16 sm[];
    uint32_t smb;
    asm("{ .reg .u64 t; cvta.to.shared.u64 t, %1; cvt.u32.u64 %0, t; }" : "=r"(smb) : "l"(sm));
    const int tid = threadIdx.x;
    const int lane = tid & 31, wid = tid >> 5;
    const int grp = lane >> 2, qid = lane & 3;
    const int warp_m = (wid & 3) * 32;
    const int warp_n = (wid >> 2) * 64;
    const int n0 = blockIdx.x * 128;
    const int m0 = blockIdx.y * 128;
    const int kz = blockIdx.z * 256;

    const int r0 = tid >> 2,         c8 = (tid & 3) << 3;
    const int r1 = (256 + tid) >> 2;

    float acc[2][8][4];
#pragma unroll
    for (int i=0;i<2;++i)
#pragma unroll
        for (int j=0;j<8;++j)
#pragma unroll
            for (int q=0;q<4;++q) acc[i][j][q] = 0.f;

    for (int it = 0; it < 8; ++it){
        int k0 = kz + it*32;
#pragma unroll
        for (int t=0; t<2; ++t){
            const __nv_bfloat16* ga0 = A + (size_t)t*4194304ull + (size_t)(m0+r0)*2048 + k0 + c8;
            const __nv_bfloat16* ga1 = A + (size_t)t*4194304ull + (size_t)(m0+r1)*2048 + k0 + c8;
            uint32_t da0 = smb + (uint32_t)(t*TERM_SZ + r0*SM_ROW + c8)*2;
            uint32_t da1 = smb + (uint32_t)(t*TERM_SZ + r1*SM_ROW + c8)*2;
            asm volatile("cp.async.cg.shared.global [%0], [%1], 16;" :: "r"(da0), "l"(ga0));
            asm volatile("cp.async.cg.shared.global [%0], [%1], 16;" :: "r"(da1), "l"(ga1));
            const __nv_bfloat16* gb0 = B + (size_t)t*524288ull + (size_t)(n0+r0)*2048 + k0 + c8;
            const __nv_bfloat16* gb1 = B + (size_t)t*524288ull + (size_t)(n0+r1)*2048 + k0 + c8;
            uint32_t db0 = smb + (uint32_t)((2+t)*TERM_SZ + r0*SM_ROW + c8)*2;
            uint32_t db1 = smb + (uint32_t)((2+t)*TERM_SZ + r1*SM_ROW + c8)*2;
            asm volatile("cp.async.cg.shared.global [%0], [%1], 16;" :: "r"(db0), "l"(gb0));
            asm volatile("cp.async.cg.shared.global [%0], [%1], 16;" :: "r"(db1), "l"(gb1));
        }
        asm volatile("cp.async.commit_group;");
        asm volatile("cp.async.wait_group 0;");
        __syncthreads();
        const __nv_bfloat16* As = sm;
        const __nv_bfloat16* Bs = sm + 2*TERM_SZ;
#pragma unroll
        for (int kk=0; kk<32; kk+=16){
            uint32_t afr[2][2][4];
#pragma unroll
            for (int t=0; t<2; ++t)
#pragma unroll
                for (int mf=0; mf<2; ++mf){
                    const __nv_bfloat16* ap = As + t*TERM_SZ + (warp_m + mf*16 + grp)*SM_ROW + kk + qid*2;
                    afr[t][mf][0] = *(const uint32_t*)(ap);
                    afr[t][mf][1] = *(const uint32_t*)(ap + 8*SM_ROW);
                    afr[t][mf][2] = *(const uint32_t*)(ap + 8);
                    afr[t][mf][3] = *(const uint32_t*)(ap + 8*SM_ROW + 8);
                }
#pragma unroll
            for (int nf=0; nf<8; ++nf){
                const __nv_bfloat16* bb = Bs + (warp_n + nf*8 + grp)*SM_ROW + kk + qid*2;
                uint32_t b0[2], b1[2];
#pragma unroll
                for (int t=0; t<2; ++t){
                    b0[t] = *(const uint32_t*)(bb + t*TERM_SZ);
                    b1[t] = *(const uint32_t*)(bb + t*TERM_SZ + 8);
                }
                mma16816(acc[0][nf], afr[0][0], b0[0], b1[0]);
                mma16816(acc[1][nf], afr[0][1], b0[0], b1[0]);
                mma16816(acc[0][nf], afr[0][0], b0[1], b1[1]);
                mma16816(acc[1][nf], afr[0][1], b0[1], b1[1]);
                mma16816(acc[0][nf], afr[1][0], b0[0], b1[0]);
                mma16816(acc[1][nf], afr[1][1], b0[0], b1[0]);
                mma16816(acc[0][nf], afr[1][0], b0[1], b1[1]);
                mma16816(acc[1][nf], afr[1][1], b0[1], b1[1]);
            }
        }
        __syncthreads();
    }

    float* pb = part + (size_t)blockIdx.z * (2000*256);
#pragma unroll
    for (int mf=0; mf<2; ++mf){
        int gm0 = m0 + warp_m + mf*16 + grp;
        int gm1 = gm0 + 8;
#pragma unroll
        for (int nf=0; nf<8; ++nf){
            int gn = n0 + warp_n + nf*8 + qid*2;
            if (gm0 < 2000){
                float2 v0 = make_float2(acc[mf][nf][0], acc[mf][nf][1]);
                *(float2*)(pb + (size_t)gm0*256 + gn) = v0;
            }
            if (gm1 < 2000){
                float2 v1 = make_float2(acc[mf][nf][2], acc[mf][nf][3]);
                *(float2*)(pb + (size_t)gm1*256 + gn) = v1;
            }
        }
    }
}

// --------- conversion kernels ---------
__device__ __forceinline__ void bf2split(float a, __nv_bfloat16& b0, __nv_bfloat16& b1){
    b0 = __float2bfloat16(a);
    float r1 = a - __bfloat162float(b0);
    b1 = __float2bfloat16(r1);
}
__device__ __forceinline__ void bf3split(float a, __nv_bfloat16& b0, __nv_bfloat16& b1, __nv_bfloat16& b2){
    b0 = __float2bfloat16(a);
    float r1 = a - __bfloat162float(b0);
    b1 = __float2bfloat16(r1);
    float r2 = r1 - __bfloat162float(b1);
    b2 = __float2bfloat16(r2);
}
__device__ __forceinline__ uint32_t bfpack(__nv_bfloat16 lo, __nv_bfloat16 hi){
    return (uint32_t)__bfloat16_as_ushort(lo) | ((uint32_t)__bfloat16_as_ushort(hi) << 16);
}
__global__ void convA_k(const float* __restrict__ A, __nv_bfloat16* __restrict__ out){
    size_t t = (size_t)blockIdx.x*256 + threadIdx.x;
    int r  = (int)(t >> 9);
    int k8 = (int)(t & 511) << 3;
    bool rin = (r < 4000);
    float v[8];
#pragma unroll
    for (int i=0;i<8;++i){ int k = k8 + i; v[i] = (rin && k < 4000) ? A[(size_t)r*4000 + k] : 0.f; }
    uint32_t p0[4], p1[4];
#pragma unroll
    for (int i=0;i<4;++i){
        __nv_bfloat16 a0,a1,b0,b1;
        bf2split(v[2*i],   a0,a1);
        bf2split(v[2*i+1], b0,b1);
        p0[i] = bfpack(a0,b0); p1[i] = bfpack(a1,b1);
    }
    size_t o = (size_t)r*4096 + k8;
    *(uint4*)(out + o)               = make_uint4(p0[0],p0[1],p0[2],p0[3]);
    *(uint4*)(out + o + 16777216ull) = make_uint4(p1[0],p1[1],p1[2],p1[3]);
}
__global__ void convB_k(const float* __restrict__ axu, const float* __restrict__ cs,
                        __nv_bfloat16* __restrict__ out){
    __shared__ float tile[32][33];
    int kt = blockIdx.x*32, nt = blockIdx.y*32;
    int tx = threadIdx.x, ty = threadIdx.y;
    for (int i=ty; i<32; i+=8){
        int k = kt + i;
        tile[i][tx] = (k < 4000) ? axu[(size_t)k*512 + nt + tx] * cs[k] : 0.f;
    }
    __syncthreads();
    for (int i=ty; i<32; i+=8){
        int n = nt + i, k = kt + tx;
        float a = tile[tx][i];
        __nv_bfloat16 b0,b1;
        bf2split(a, b0,b1);
        size_t o = (size_t)n*4096 + k;
        out[o] = b0; out[o + 1048576ull] = b1;
    }
}
__global__ void convNT_k(const float* __restrict__ in, __nv_bfloat16* __restrict__ out){
    int t = blockIdx.x*256 + threadIdx.x;
    int r  = t >> 5;
    int c8 = (t & 31) << 3;
    bool rin = (r < 2000);
    float v[8];
#pragma unroll
    for (int i=0;i<8;++i) v[i] = rin ? in[(size_t)r*256 + c8 + i] : 0.f;
    uint32_t p0[4], p1[4], p2[4];
#pragma unroll
    for (int i=0;i<4;++i){
        __nv_bfloat16 a0,a1,a2,b0,b1,b2;
        bf3split(v[2*i],   a0,a1,a2);
        bf3split(v[2*i+1], b0,b1,b2);
        p0[i] = bfpack(a0,b0); p1[i] = bfpack(a1,b1); p2[i] = bfpack(a2,b2);
    }
    size_t o = (size_t)r*256 + c8;
    *(uint4*)(out + o)              = make_uint4(p0[0],p0[1],p0[2],p0[3]);
    *(uint4*)(out + o + 524288ull)  = make_uint4(p1[0],p1[1],p1[2],p1[3]);
    *(uint4*)(out + o + 1048576ull) = make_uint4(p2[0],p2[1],p2[2],p2[3]);
}
// generic fp32 [rows, c8cnt*8] -> 3-term bf16 padded; grid covers padrows*c8cnt/32 uint4s.
__global__ void conv3_k(const float* __restrict__ in, __nv_bfloat16* __restrict__ out,
                        int rows, int c8cnt, size_t term){
    int t = blockIdx.x*256 + threadIdx.x;
    int r  = t / c8cnt;
    int c8 = (t % c8cnt) << 3;
    int cols = c8cnt << 3;
    bool rin = (r < rows);
    float v[8];
#pragma unroll
    for (int i=0;i<8;++i) v[i] = rin ? in[(size_t)r*cols + c8 + i] : 0.f;
    uint32_t p0[4], p1[4], p2[4];
#pragma unroll
    for (int i=0;i<4;++i){
        __nv_bfloat16 a0,a1,a2,b0,b1,b2;
        bf3split(v[2*i],   a0,a1,a2);
        bf3split(v[2*i+1], b0,b1,b2);
        p0[i] = bfpack(a0,b0); p1[i] = bfpack(a1,b1); p2[i] = bfpack(a2,b2);
    }
    size_t o = (size_t)r*cols + c8;
    *(uint4*)(out + o)          = make_uint4(p0[0],p0[1],p0[2],p0[3]);
    *(uint4*)(out + o + term)   = make_uint4(p1[0],p1[1],p1[2],p1[3]);
    *(uint4*)(out + o + 2*term) = make_uint4(p2[0],p2[1],p2[2],p2[3]);
}
// w[K,N] -> out[3][N][K] transposed 3-term. grid N, block 256.
__global__ void packW_k(const float* __restrict__ w, __nv_bfloat16* __restrict__ out,
                        int N, int K){
    int n = blockIdx.x;
    size_t term = (size_t)N*K;
    for (int k = threadIdx.x; k < K; k += 256){
        float a = w[(size_t)k*N + n];
        __nv_bfloat16 b0,b1,b2;
        bf3split(a, b0,b1,b2);
        size_t o = (size_t)n*K + k;
        out[o] = b0; out[o + term] = b1; out[o + 2*term] = b2;
    }
}
// x [4000,256] -> [3][4096][256] bf16 3-term. grid 512, block 256.
__global__ void convX_k(const float* __restrict__ in, __nv_bfloat16* __restrict__ out){
    int t = blockIdx.x*256 + threadIdx.x;
    int r  = t >> 5;
    int c8 = (t & 31) << 3;
    bool rin = (r < 4000);
    float v[8];
#pragma unroll
    for (int i=0;i<8;++i) v[i] = rin ? in[(size_t)r*256 + c8 + i] : 0.f;
    uint32_t p0[4], p1[4], p2[4];
#pragma unroll
    for (int i=0;i<4;++i){
        __nv_bfloat16 a0,a1,a2,b0,b1,b2;
        bf3split(v[2*i],   a0,a1,a2);
        bf3split(v[2*i+1], b0,b1,b2);
        p0[i] = bfpack(a0,b0); p1[i] = bfpack(a1,b1); p2[i] = bfpack(a2,b2);
    }
    size_t o = (size_t)r*256 + c8;
    *(uint4*)(out + o)               = make_uint4(p0[0],p0[1],p0[2],p0[3]);
    *(uint4*)(out + o + 1048576ull)  = make_uint4(p1[0],p1[1],p1[2],p1[3]);
    *(uint4*)(out + o + 2097152ull)  = make_uint4(p2[0],p2[1],p2[2],p2[3]);
}
// [wa|wu] pack for gnn (unchanged from R12)
__global__ void packW3_k(const float* __restrict__ wa, const float* __restrict__ wu,
                         const float* __restrict__ ba, const float* __restrict__ bu,
                         __nv_bfloat16* __restrict__ Bw, float* __restrict__ bcat){
    int n = blockIdx.x, k = threadIdx.x;
    float w = (n < 256) ? wa[(size_t)k*256 + n] : wu[(size_t)k*256 + (n-256)];
    __nv_bfloat16 b0,b1,b2;
    bf3split(w, b0,b1,b2);
    size_t o = (size_t)n*256 + k;
    Bw[o] = b0; Bw[o + 131072ull] = b1; Bw[o + 262144ull] = b2;
    if (k == 0) bcat[n] = (n < 256) ? ba[n] : bu[n-256];
}
__global__ void convS0_k(const float* __restrict__ s0, __nv_bfloat16* __restrict__ out){
    __shared__ float tile[32][33];
    int c0 = blockIdx.x*32, rb = blockIdx.y*32;
    int tx = threadIdx.x, ty = threadIdx.y;
    for (int i=ty; i<32; i+=8){
        int r = rb + i, c = c0 + tx;
        tile[i][tx] = (r < 2000 && c < 2000) ? s0[(size_t)r*2000 + c] : 0.f;
    }
    __syncthreads();
    for (int i=ty; i<32; i+=8){
        int r = rb + i, c = c0 + tx;
        float a = tile[i][tx];
        __nv_bfloat16 b0,b1;
        bf2split(a, b0,b1);
        size_t o = (size_t)r*2048 + c;
        out[o] = b0; out[o + 4194304ull] = b1;
        float at = tile[tx][i];
        __nv_bfloat16 t0,t1;
        bf2split(at, t0,t1);
        size_t ot = 8388608ull + (size_t)(c0 + i)*2048 + (rb + tx);
        out[ot] = t0; out[ot + 4194304ull] = t1;
    }
}
__global__ void convCGB_k(const float* __restrict__ x, const float* __restrict__ sc,
                          __nv_bfloat16* __restrict__ out){
    __shared__ float tile[32][33];
    int kt = blockIdx.x*32, nt = blockIdx.y*32;
    int tx = threadIdx.x, ty = threadIdx.y;
    for (int i=ty; i<32; i+=8){
        int k = kt + i;
        tile[i][tx] = (k < 2000) ? x[(size_t)k*256 + nt + tx] * sc[k] : 0.f;
    }
    __syncthreads();
    for (int i=ty; i<32; i+=8){
        int n = nt + i, k = kt + tx;
        float a = tile[tx][i];
        __nv_bfloat16 b0,b1;
        bf2split(a, b0,b1);
        size_t o = (size_t)n*2048 + k;
        out[o] = b0; out[o + 524288ull] = b1;
    }
}

// ---------------- generic fp32 GEMM ----------------
#define BM 128
#define BN 64
#define BK 16

template<bool TA, bool TB>
__global__ __launch_bounds__(256) void gemm_k(
    int M, int N, int K, int chunk, size_t pstride,
    const float* __restrict__ A, int lda,
    const float* __restrict__ B, int ldb,
    float* __restrict__ C, int ldc,
    const float* __restrict__ bias,
    const float* __restrict__ kscale,
    const float* __restrict__ mscale,
    const float* __restrict__ addend, int ldadd,
    int act, int accum,
    const float* __restrict__ xsq, const float* __restrict__ ysq,
    float* __restrict__ gmax)
{
    __shared__ float As[BK][BM+4];
    __shared__ float Bs[BK][BN+4];
    int tid = threadIdx.x;
    int m0 = blockIdx.y * BM;
    int n0 = blockIdx.x * BN;
    int tx = tid & 15, ty = tid >> 4;
    int ml = ty*8, nl = tx*4;

    int kbeg = blockIdx.z * chunk;
    int kend = kbeg + chunk; if (kend > K) kend = K;

    float acc[8][4];
#pragma unroll
    for (int i=0;i<8;++i)
#pragma unroll
        for (int j=0;j<4;++j) acc[i][j] = 0.f;

    for (int k0 = kbeg; k0 < kend; k0 += BK){
        if (!TA){
#pragma unroll
            for (int it=0; it<2; ++it){
                int idx = it*256 + tid;
                int row = idx >> 2;
                int kc  = (idx & 3) << 2;
                float4 vv = make_float4(0.f,0.f,0.f,0.f);
                int gm = m0 + row;
                if (gm < M) vv = *(const float4*)(A + (size_t)gm*lda + k0 + kc);
                As[kc+0][row]=vv.x; As[kc+1][row]=vv.y; As[kc+2][row]=vv.z; As[kc+3][row]=vv.w;
            }
        } else {
#pragma unroll
            for (int it=0; it<2; ++it){
                int idx = it*256 + tid;
                int kk = idx >> 5;
                int mc = (idx & 31) << 2;
                float4 vv = make_float4(0.f,0.f,0.f,0.f);
                int gm = m0 + mc;
                if (gm < M) vv = *(const float4*)(A + (size_t)(k0+kk)*lda + gm);
                *(float4*)(&As[kk][mc]) = vv;
            }
        }
        if (!TB){
            int kk = tid >> 4;
            int nc = (tid & 15) << 2;
            float4 vv = make_float4(0.f,0.f,0.f,0.f);
            int gn = n0 + nc;
            if (gn < N) vv = *(const float4*)(B + (size_t)(k0+kk)*ldb + gn);
            if (kscale){ float s = kscale[k0+kk]; vv.x*=s; vv.y*=s; vv.z*=s; vv.w*=s; }
            *(float4*)(&Bs[kk][nc]) = vv;
        } else {
            int nr = tid >> 2;
            int kc = (tid & 3) << 2;
            float4 vv = make_float4(0.f,0.f,0.f,0.f);
            int gn = n0 + nr;
            if (gn < N) vv = *(const float4*)(B + (size_t)gn*ldb + k0 + kc);
            if (kscale){
                vv.x *= kscale[k0+kc+0]; vv.y *= kscale[k0+kc+1];
                vv.z *= kscale[k0+kc+2]; vv.w *= kscale[k0+kc+3];
            }
            Bs[kc+0][nr]=vv.x; Bs[kc+1][nr]=vv.y; Bs[kc+2][nr]=vv.z; Bs[kc+3][nr]=vv.w;
        }
        __syncthreads();
#pragma unroll
        for (int kk=0; kk<BK; ++kk){
            float4 a0 = *(const float4*)(&As[kk][ml]);
            float4 a1 = *(const float4*)(&As[kk][ml+4]);
            float4 b0 = *(const float4*)(&Bs[kk][nl]);
            float av[8] = {a0.x,a0.y,a0.z,a0.w,a1.x,a1.y,a1.z,a1.w};
            float bv[4] = {b0.x,b0.y,b0.z,b0.w};
#pragma unroll
            for (int i=0;i<8;++i)
#pragma unroll
                for (int j=0;j<4;++j) acc[i][j] = fmaf(av[i], bv[j], acc[i][j]);
        }
        __syncthreads();
    }

    if (gridDim.z > 1){
        float* Cp = C + (size_t)blockIdx.z * pstride;
#pragma unroll
        for (int i=0;i<8;++i){
            int gm = m0 + ml + i;
            if (gm < M){
#pragma unroll
                for (int j=0;j<4;++j){
                    int gn = n0 + nl + j;
                    if (gn < N) Cp[(size_t)gm*ldc + gn] = acc[i][j];
                }
            }
        }
        return;
    }

    float dmax = 0.f;
#pragma unroll
    for (int i=0;i<8;++i){
        int gm = m0 + ml + i;
        if (gm < M){
#pragma unroll
            for (int j=0;j<4;++j){
                int gn = n0 + nl + j;
                if (gn < N){
                    float v = acc[i][j];
                    size_t cidx = (size_t)gm*ldc + gn;
                    if (accum)  v += C[cidx];
                    if (addend) v += addend[(size_t)gm*ldadd + gn];
                    if (bias)   v += bias[gn];
                    if (act==1)      v = fmaxf(v, 0.f);
                    else if (act==2) v = 1.f/(1.f+expf(-v));
                    else if (act==3){
                        v = sqrtf(fmaxf(xsq[gm]+ysq[gn]-2.f*v, 0.f));
                        dmax = fmaxf(dmax, v);
                    }
                    if (mscale) v *= mscale[gm];
                    C[cidx] = v;
                }
            }
        }
    }
    if (act==3){
        __shared__ float red[256];
        red[tid] = dmax; __syncthreads();
        for (int s=128;s;s>>=1){ if (tid<s) red[tid]=fmaxf(red[tid],red[tid+s]); __syncthreads(); }
        if (tid==0) atomicMax((int*)gmax, __float_as_int(red[0]));
    }
}

// ---------------- split-K reducer ----------------
__global__ void reduce_k(const float* __restrict__ part, size_t pstride, int SK,
                         const float* __restrict__ addend, int ldadd,
                         const float* __restrict__ bias,
                         const float* __restrict__ rowscale,
                         float* __restrict__ out,
                         float* __restrict__ sqout, int mode)
{
    int row = blockIdx.x, t = threadIdx.x;
    float v = 0.f;
    for (int z=0; z<SK; ++z) v += part[(size_t)z*pstride + (size_t)row*256 + t];
    if (addend) v += addend[(size_t)row*ldadd + t];
    if (bias)   v += bias[t];
    if (mode==1){
        float s = blockReduceSum256(v*v);
        v /= fmaxf(sqrtf(s), 1e-12f);
        if (sqout && t==0) sqout[row] = 1.f;
    } else if (mode==2){
        v = 1.f/(1.f+expf(-v));
        float s = blockReduceSum256(v*v);
        if (sqout && t==0) sqout[row] = s;
    }
    if (rowscale) v *= rowscale[row];
    out[(size_t)row*256 + t] = v;
}

// ---------------- elementwise / misc kernels ----------------
__global__ void zero_k(float* p, int n){
    int i = blockIdx.x*blockDim.x + threadIdx.x;
    if (i < n) p[i] = 0.f;
}
__global__ void recip_clamp_k(float* p, int n){
    int i = blockIdx.x*blockDim.x + threadIdx.x;
    if (i < n) p[i] = 1.f / fmaxf(p[i], 1e-12f);
}
__global__ void simfin_k(float* __restrict__ p, const float* __restrict__ gmax, int n){
    int i = blockIdx.x*blockDim.x + threadIdx.x;
    if (i < n){
        float inv = 1.f / gmax[0];
        p[i] = 1.f - p[i]*inv;
    }
}
__global__ void colabs_k(const float* __restrict__ A, float* __restrict__ acc){
    int j  = blockIdx.x*256 + threadIdx.x;
    int r0 = blockIdx.y*125;
    if (j >= 4000) return;
    float s = 0.f;
    for (int i=0;i<125;++i) s += fabsf(A[(size_t)(r0+i)*4000 + j]);
    atomicAdd(&acc[j], s);
}
__global__ void ssym_k(const float* __restrict__ A, float* __restrict__ S){
    int i = blockIdx.x, j = threadIdx.x;
    S[i*256+j] = 0.5f*(A[i*256+j] + A[j*256+i]);
}
__global__ void softmax_k(float* __restrict__ s0base){
    int z = blockIdx.y, row = blockIdx.x, tid = threadIdx.x;
    float* p = s0base + (size_t)z*4000000 + (size_t)row*2000;
    float a[8]; float mx = -1e30f;
#pragma unroll
    for (int i=0;i<8;++i){
        int c = tid + i*256;
        if (c < 2000){ a[i] = 200.f*p[c]; mx = fmaxf(mx, a[i]); }
        else a[i] = -1e30f;
    }
    float rowmax = blockReduceMax256(mx);
    float Mx = fmaxf(rowmax, 0.f);
    float lsum = 0.f;
#pragma unroll
    for (int i=0;i<8;++i){
        int c = tid + i*256;
        if (c < 2000){ a[i] = expf(a[i]-Mx); lsum += a[i]; }
    }
    float tot = blockReduceSum256(lsum) + 2000.f*expf(-Mx);
    float inv = 1.f/tot;
#pragma unroll
    for (int i=0;i<8;++i){
        int c = tid + i*256;
        if (c < 2000) p[c] = a[i]*inv + 1e-4f;
    }
}
__global__ void sink_col_k(const float* __restrict__ s0base, const float* __restrict__ vraw,
                           float* __restrict__ uraw, int first){
    int z = blockIdx.z;
    const float* s0 = s0base + (size_t)z*4000000;
    __shared__ float Rs[125];
    int r0 = blockIdx.y*125;
    if (threadIdx.x < 125)
        Rs[threadIdx.x] = first ? 1.f : 1.f/vraw[z*2048 + r0 + threadIdx.x];
    __syncthreads();
    int j = blockIdx.x*256 + threadIdx.x;
    if (j < 2000){
        float s = 0.f;
        for (int i=0;i<125;++i) s += s0[(size_t)(r0+i)*2000 + j]*Rs[i];
        atomicAdd(&uraw[z*2048 + j], s);
    }
}
__global__ void sink_row_k(const float* __restrict__ s0base, const float* __restrict__ uraw,
                           float* __restrict__ vraw){
    int z = blockIdx.y;
    const float* s0 = s0base + (size_t)z*4000000;
    __shared__ float Cs[2000];
    for (int i=threadIdx.x; i<2000; i+=256) Cs[i] = 1.f/uraw[z*2048 + i];
    __syncthreads();
    int w = threadIdx.x>>5, lane = threadIdx.x&31;
    int row = blockIdx.x*8 + w;
    const float* pr = s0 + (size_t)row*2000;
    float s = 0.f;
    for (int j=lane; j<2000; j+=32) s += pr[j]*Cs[j];
#pragma unroll
    for (int o=16;o;o>>=1) s += __shfl_down_sync(0xffffffffu, s, o);
    if (lane==0) vraw[z*2048 + row] = s;
}
__global__ void scales_k(const float* __restrict__ uraw, const float* __restrict__ vraw,
                         float* __restrict__ Cf, float* __restrict__ Rf){
    int z = blockIdx.y;
    int i = blockIdx.x*256 + threadIdx.x;
    if (i < 2000){
        Cf[z*2048+i] = 1.f/uraw[z*2048+i];
        Rf[z*2048+i] = 1.f/vraw[z*2048+i];
    }
}
__global__ void write_s_k(float* __restrict__ out, const float* __restrict__ s0base,
                          const float* __restrict__ Rf, const float* __restrict__ Cf){
    int row = blockIdx.y;
    int col = blockIdx.x*256 + threadIdx.x;
    if (col >= 4000) return;
    float v = 0.f;
    if (row < 2000 && col < 2000)
        v = s0base[(size_t)row*2000 + col] * Rf[row] * Cf[col];
    else if (row >= 2000 && col >= 2000)
        v = s0base[4000000 + (size_t)(row-2000)*2000 + (col-2000)]
            * Rf[2048 + row-2000] * Cf[2048 + col-2000];
    out[(size_t)row*4000 + col] = v;
}

// ---------------- host-side GEMM dispatch ----------------
static void run_gemm(int ta, int tb, int M, int N, int K,
                     const float* A, int lda, const float* B, int ldb,
                     float* C, int ldc,
                     const float* bias, const float* ks, const float* ms,
                     const float* add, int ldadd, int act, int accum,
                     const float* xsq, const float* ysq, float* gmax)
{
    dim3 grid((N+BN-1)/BN, (M+BM-1)/BM, 1);
    if (!ta && !tb)      gemm_k<false,false><<<grid,256>>>(M,N,K,K,0,A,lda,B,ldb,C,ldc,bias,ks,ms,add,ldadd,act,accum,xsq,ysq,gmax);
    else if (!ta && tb)  gemm_k<false,true ><<<grid,256>>>(M,N,K,K,0,A,lda,B,ldb,C,ldc,bias,ks,ms,add,ldadd,act,accum,xsq,ysq,gmax);
    else                 gemm_k<true ,false><<<grid,256>>>(M,N,K,K,0,A,lda,B,ldb,C,ldc,bias,ks,ms,add,ldadd,act,accum,xsq,ysq,gmax);
}
static void run_gemm_split(int ta, int M, int N, int K,
                           const float* A, int lda, const float* B, int ldb,
                           float* part, const float* ks, int SK, int chunk)
{
    dim3 grid((N+BN-1)/BN, (M+BM-1)/BM, SK);
    size_t ps = (size_t)M*N;
    if (!ta) gemm_k<false,false><<<grid,256>>>(M,N,K,chunk,ps,A,lda,B,ldb,part,N,0,ks,0,0,0,0,0,0,0,0);
    else     gemm_k<true ,false><<<grid,256>>>(M,N,K,chunk,ps,A,lda,B,ldb,part,N,0,ks,0,0,0,0,0,0,0,0);
}

extern "C" void kernel_launch(void* const* d_in, const int* in_sizes, int n_in,
                              void* d_out, int out_size)
{
    (void)in_sizes; (void)n_in; (void)out_size;
    const float* emb1      = (const float*)d_in[0];
    const float* emb2      = (const float*)d_in[1];
    const float* edge1     = (const float*)d_in[2];
    const float* edge2     = (const float*)d_in[3];
    const float* Asrc      = (const float*)d_in[4];
    const float* Atgt      = (const float*)d_in[5];
    const float* fc1n_w    = (const float*)d_in[6];
    const float* fc1n_b    = (const float*)d_in[7];
    const float* fc2n_w    = (const float*)d_in[8];
    const float* fc2n_b    = (const float*)d_in[9];
    const float* fc1e_w    = (const float*)d_in[10];
    const float* fc1e_b    = (const float*)d_in[11];
    const float* fc2e_w    = (const float*)d_in[12];
    const float* fc2e_b    = (const float*)d_in[13];
    const float* gnn_a_w   = (const float*)d_in[14];
    const float* gnn_a_b   = (const float*)d_in[15];
    const float* gnn_u_w   = (const float*)d_in[16];
    const float* gnn_u_b   = (const float*)d_in[17];
    const float* aff_A     = (const float*)d_in[18];
    const float* cg_w      = (const float*)d_in[19];
    const float* cg_b      = (const float*)d_in[20];

    float* out_s  = (float*)d_out;
    float* out_kp = out_s + 16000000;
    float* out_ke = out_s + 20000000;

    float *h,*xA1,*xB1,*xA2,*xB2,*axu,*tc1,*tc2,*s0,*T1,*Ssym,*bcat;
    float *cs,*u,*v,*Rf,*Cf,*sq,*gmax,*part;
    __nv_bfloat16 *Abf, *Bbf, *ntA, *ntB, *s0bf, *cgB, *Xbf, *Bw, *w1n, *w1e, *w2n, *w2e;
    cudaGetSymbolAddress((void**)&h,    g_h);
    cudaGetSymbolAddress((void**)&xA1,  g_xA1);
    cudaGetSymbolAddress((void**)&xB1,  g_xB1);
    cudaGetSymbolAddress((void**)&xA2,  g_xA2);
    cudaGetSymbolAddress((void**)&xB2,  g_xB2);
    cudaGetSymbolAddress((void**)&axu,  g_axu);
    cudaGetSymbolAddress((void**)&tc1,  g_tc1);
    cudaGetSymbolAddress((void**)&tc2,  g_tc2);
    cudaGetSymbolAddress((void**)&s0,   g_s0);
    cudaGetSymbolAddress((void**)&T1,   g_T1);
    cudaGetSymbolAddress((void**)&Ssym, g_Ssym);
    cudaGetSymbolAddress((void**)&bcat, g_bcat);
    cudaGetSymbolAddress((void**)&cs,   g_cs);
    cudaGetSymbolAddress((void**)&u,    g_u);
    cudaGetSymbolAddress((void**)&v,    g_v);
    cudaGetSymbolAddress((void**)&Rf,   g_Rf);
    cudaGetSymbolAddress((void**)&Cf,   g_Cf);
    cudaGetSymbolAddress((void**)&sq,   g_sq);
    cudaGetSymbolAddress((void**)&gmax, g_gmax);
    cudaGetSymbolAddress((void**)&part, g_part);
    cudaGetSymbolAddress((void**)&Abf,  g_Abf);
    cudaGetSymbolAddress((void**)&Bbf,  g_Bbf);
    cudaGetSymbolAddress((void**)&ntA,  g_ntA);
    cudaGetSymbolAddress((void**)&ntB,  g_ntB);
    cudaGetSymbolAddress((void**)&s0bf, g_s0bf);
    cudaGetSymbolAddress((void**)&cgB,  g_cgB);
    cudaGetSymbolAddress((void**)&Xbf,  g_Xbf);
    cudaGetSymbolAddress((void**)&Bw,   g_Bw);
    cudaGetSymbolAddress((void**)&w1n,  g_w1n);
    cudaGetSymbolAddress((void**)&w1e,  g_w1e);
    cudaGetSymbolAddress((void**)&w2n,  g_w2n);
    cudaGetSymbolAddress((void**)&w2e,  g_w2e);

    cudaFuncSetAttribute(mma_big_k,  cudaFuncAttributeMaxDynamicSharedMemorySize, MMA_SMEM);
    cudaFuncSetAttribute(mma_nt_k<0>, cudaFuncAttributeMaxDynamicSharedMemorySize, NT_SMEM);
    cudaFuncSetAttribute(mma_nt_k<3>, cudaFuncAttributeMaxDynamicSharedMemorySize, NT_SMEM);
    cudaFuncSetAttribute(mma_cg_k,   cudaFuncAttributeMaxDynamicSharedMemorySize, CG_SMEM);
    cudaFuncSetAttribute((mma_ab_k<4,128,2048,512,1>),  cudaFuncAttributeMaxDynamicSharedMemorySize, NT_SMEM);
    cudaFuncSetAttribute((mma_ab_k<16,512,2048,256,0>), cudaFuncAttributeMaxDynamicSharedMemorySize, NT_SMEM);
    cudaFuncSetAttribute((mma_ab_k<8,256,4096,512,1>),  cudaFuncAttributeMaxDynamicSharedMemorySize, NT_SMEM);

    float* cur[2] = {xA1, xA2};
    float* alt[2] = {xB1, xB2};

    // ---------- A conversions (once; A is constant across layers) ----------
    convA_k<<<8192,256>>>(Asrc, Abf);
    convA_k<<<8192,256>>>(Atgt, Abf + 2ull*4096*4096);

    // ---------- Stage A: node/edge embedding MLPs (tensor path) ----------
    packW_k<<<512,256>>>(fc1n_w, w1n, 512, 128);
    packW_k<<<512,256>>>(fc1e_w, w1e, 512, 128);
    packW_k<<<256,256>>>(fc2n_w, w2n, 256, 512);
    packW_k<<<256,256>>>(fc2e_w, w2e, 256, 512);

    const float* embs[4]  = {emb1, emb2, edge1, edge2};
    const __nv_bfloat16* w1s[4] = {w1n, w1n, w1e, w1e};
    const __nv_bfloat16* w2s[4] = {w2n, w2n, w2e, w2e};
    const float* b1s[4] = {fc1n_b, fc1n_b, fc1e_b, fc1e_b};
    const float* b2s[4] = {fc2n_b, fc2n_b, fc2e_b, fc2e_b};
    float* outs[4] = {xA1, xA2, xA1+2000*256, xA2+2000*256};
    int modes[4] = {1,1,2,2};
    for (int br=0; br<4; ++br){
        conv3_k<<<128,256>>>(embs[br], ntA, 2000, 16, 2048*128);    // emb 3-term in ntA
        mma_ab_k<4,128,2048,512,1><<<dim3(4,16),256,NT_SMEM>>>(ntA, w1s[br], b1s[br], h, 2000, 512);
        conv3_k<<<512,256>>>(h, Xbf, 2000, 64, 2048*512);           // h 3-term in Xbf
        mma_ab_k<16,512,2048,256,0><<<dim3(2,16),256,NT_SMEM>>>(Xbf, w2s[br], 0, part, 2000, 256);
        reduce_k<<<2000,256>>>(part, 0, 1, 0,0, b2s[br], 0, outs[br], sq + br*2048, modes[br]);
    }

    // ---------- Kp / Ke pairwise similarity (tensor NT path) ----------
    zero_k<<<1,32>>>(gmax, 2);
    convNT_k<<<256,256>>>(cur[0], ntA);
    convNT_k<<<256,256>>>(cur[1], ntB);
    mma_nt_k<3><<<dim3(16,16),256,NT_SMEM>>>(ntA, ntB, out_kp, sq+0, sq+2048, gmax+0);
    convNT_k<<<256,256>>>(cur[0]+2000*256, ntA);
    convNT_k<<<256,256>>>(cur[1]+2000*256, ntB);
    mma_nt_k<3><<<dim3(16,16),256,NT_SMEM>>>(ntA, ntB, out_ke, sq+4096, sq+6144, gmax+1);
    simfin_k<<<(4000000+255)/256,256>>>(out_kp, gmax+0, 4000000);
    simfin_k<<<(4000000+255)/256,256>>>(out_ke, gmax+1, 4000000);

    // ---------- A column L1 sums -> reciprocal scales ----------
    zero_k<<<(8192+255)/256,256>>>(cs, 8192);
    colabs_k<<<dim3(16,32),256>>>(Asrc, cs);
    colabs_k<<<dim3(16,32),256>>>(Atgt, cs+4096);
    recip_clamp_k<<<(8192+255)/256,256>>>(cs, 8192);

    // ---------- GNN layers ----------
    for (int i=0; i<3; ++i){
        packW3_k<<<512,256>>>(gnn_a_w + (size_t)i*65536, gnn_u_w + (size_t)i*65536,
                              gnn_a_b + (size_t)i*256,   gnn_u_b + (size_t)i*256,
                              Bw, bcat);

        for (int g=0; g<2; ++g){
            convX_k<<<512,256>>>(cur[g], Xbf);
            mma_ab_k<8,256,4096,512,1><<<dim3(4,32),256,NT_SMEM>>>(Xbf, Bw, bcat, axu, 4000, 512);
            convB_k<<<dim3(128,8),dim3(32,8)>>>(axu, cs + g*4096, Bbf);
            mma_big_k<<<dim3(2,32,4),256,MMA_SMEM>>>(Abf + (size_t)g*2*4096*4096, Bbf, part);
            reduce_k<<<4000,256>>>(part, 4000*256, 4, axu+256,512, 0, 0, alt[g], 0, 1);
            float* t_ = cur[g]; cur[g] = alt[g]; alt[g] = t_;
        }

        if (i >= 1){
            ssym_k<<<256,256>>>(aff_A + (size_t)i*65536, Ssym);
            for (int z=0; z<2; ++z){
                size_t off = (size_t)z*2000*256;
                run_gemm_split(0, 2000,256,256, cur[0]+off,256, Ssym,256, part, 0, 2, 128);
                reduce_k<<<2000,256>>>(part, 2000*256, 2, 0,0, 0, 0, T1, 0, 0);
                convNT_k<<<256,256>>>(T1, ntA);
                convNT_k<<<256,256>>>(cur[1]+off, ntB);
                mma_nt_k<0><<<dim3(16,16),256,NT_SMEM>>>(ntA, ntB, s0 + (size_t)z*4000000, 0,0,0);
            }
            softmax_k<<<dim3(2000,2),256>>>(s0);
            for (int t=0; t<10; ++t){
                if ((t & 1) == 0){
                    zero_k<<<(4096+255)/256,256>>>(u, 4096);
                    sink_col_k<<<dim3(8,16,2),256>>>(s0, v, u, (t==0)?1:0);
                } else {
                    sink_row_k<<<dim3(250,2),256>>>(s0, u, v);
                }
            }
            scales_k<<<dim3(8,2),256>>>(u, v, Cf, Rf);

            if (i == 1){
                for (int z=0; z<2; ++z){
                    size_t off = (size_t)z*2000*256;
                    convS0_k<<<dim3(64,64),dim3(32,8)>>>(s0 + (size_t)z*4000000, s0bf);
                    convCGB_k<<<dim3(64,8),dim3(32,8)>>>(cur[1]+off, Cf+z*2048, cgB);
                    mma_cg_k<<<dim3(2,16,8),256,CG_SMEM>>>(s0bf, cgB, part);
                    reduce_k<<<2000,256>>>(part, 2000*256, 8, 0,0, 0, Rf+z*2048, tc1+off, 0, 0);
                    convCGB_k<<<dim3(64,8),dim3(32,8)>>>(cur[0]+off, Rf+z*2048, cgB);
                    mma_cg_k<<<dim3(2,16,8),256,CG_SMEM>>>(s0bf + 8388608ull, cgB, part);
                    reduce_k<<<2000,256>>>(part, 2000*256, 8, 0,0, 0, Cf+z*2048, tc2+off, 0, 0);
                }
                run_gemm(0,0, 4000,256,256, cur[0],256, cg_w,256,        alt[0],256, cg_b,0,0,0,0,0,0,0,0,0);
                run_gemm(0,0, 4000,256,256, tc1,256,    cg_w+65536,256,  alt[0],256, 0,0,0,0,0,0,1,0,0,0);
                run_gemm(0,0, 4000,256,256, cur[1],256, cg_w,256,        alt[1],256, cg_b,0,0,0,0,0,0,0,0,0);
                run_gemm(0,0, 4000,256,256, tc2,256,    cg_w+65536,256,  alt[1],256, 0,0,0,0,0,0,1,0,0,0);
                float* t0 = cur[0]; cur[0] = alt[0]; alt[0] = t0;
                float* t1 = cur[1]; cur[1] = alt[1]; alt[1] = t1;
            }
            if (i == 2){
                write_s_k<<<dim3(16,4000),256>>>(out_s, s0, Rf, Cf);
            }
        }
    }
}

// round 14
// speedup vs baseline: 1.0898x; 1.0898x over previous
#include <cuda_runtime.h>
#include <cuda_bf16.h>
#include <cstdint>
#include <math.h>

// ---------------- static scratch (allocation-free rule) ----------------
__device__ float g_h   [2000*512];
__device__ float g_xA1 [4000*256];
__device__ float g_xB1 [4000*256];
__device__ float g_xA2 [4000*256];
__device__ float g_xB2 [4000*256];
__device__ float g_axu [4000*512];
__device__ float g_tc1 [4000*256];
__device__ float g_tc2 [4000*256];
__device__ float g_s0  [2u*2000*2000];
__device__ float g_T1  [2000*256];
__device__ float g_Ssym[256*256];
__device__ float g_bcat[512];
__device__ float g_cs  [2*4096];
__device__ float g_u   [2*2048];
__device__ float g_v   [2*2048];
__device__ float g_Rf  [2*2048];
__device__ float g_Cf  [2*2048];
__device__ float g_sq  [4*2048];
__device__ float g_gmax[2];
__device__ float g_part[5u*4000*256];                 // split-K partials
__device__ __nv_bfloat16 g_Abf[2ull*2*4096*4096];     // A 2-term bf16 (both graphs, padded)
__device__ __nv_bfloat16 g_Bbf[2ull*256*4096];        // ax^T 2-term bf16 (padded)
__device__ __nv_bfloat16 g_ntA[3u*2048*256];          // NT operand A 3-term
__device__ __nv_bfloat16 g_ntB[3u*2048*256];          // NT operand B 3-term
__device__ __nv_bfloat16 g_s0bf[2ull*2*2048*2048];    // s0 2-term, normal + transposed
__device__ __nv_bfloat16 g_cgB [2u*256*2048];         // cross-graph B 2-term transposed
__device__ __nv_bfloat16 g_Xbf [3u*4096*256];         // x 3-term (padded rows)
__device__ __nv_bfloat16 g_Bw  [3u*512*256];          // [wa|wu]^T 3-term

// ---------------- reductions ----------------
__device__ __forceinline__ float warpReduceSum(float v){
#pragma unroll
    for (int o=16;o;o>>=1) v += __shfl_xor_sync(0xffffffffu, v, o);
    return v;
}
__device__ __forceinline__ float warpReduceMax(float v){
#pragma unroll
    for (int o=16;o;o>>=1) v = fmaxf(v, __shfl_xor_sync(0xffffffffu, v, o));
    return v;
}
__device__ __forceinline__ float blockReduceSum256(float v){
    __shared__ float sm[8];
    float w = warpReduceSum(v);
    int wi = threadIdx.x>>5, ln = threadIdx.x&31;
    if (ln==0) sm[wi] = w;
    __syncthreads();
    if (wi==0){ float t = (ln<8)?sm[ln]:0.f; t = warpReduceSum(t); if (ln==0) sm[0]=t; }
    __syncthreads();
    float r = sm[0];
    __syncthreads();
    return r;
}
__device__ __forceinline__ float blockReduceMax256(float v){
    __shared__ float sm[8];
    float w = warpReduceMax(v);
    int wi = threadIdx.x>>5, ln = threadIdx.x&31;
    if (ln==0) sm[wi] = w;
    __syncthreads();
    if (wi==0){ float t = (ln<8)?sm[ln]:-1e30f; t = warpReduceMax(t); if (ln==0) sm[0]=t; }
    __syncthreads();
    float r = sm[0];
    __syncthreads();
    return r;
}

// ================= mma.sync primitive =================
__device__ __forceinline__ void mma16816(float* d, const uint32_t* a, uint32_t b0, uint32_t b1){
    asm volatile(
        "mma.sync.aligned.m16n8k16.row.col.f32.bf16.bf16.f32 "
        "{%0,%1,%2,%3}, {%4,%5,%6,%7}, {%8,%9}, {%0,%1,%2,%3};"
        : "+f"(d[0]), "+f"(d[1]), "+f"(d[2]), "+f"(d[3])
        : "r"(a[0]), "r"(a[1]), "r"(a[2]), "r"(a[3]), "r"(b0), "r"(b1));
}

#define SM_ROW 40                 // 32 k + 8 pad bf16 (80 B rows, 16B-aligned)
#define TERM_SZ (128*SM_ROW)

// ======== big GEMM: 2-term/3-product (positive operands), unchanged ========
#define BUF_SZ  (4*TERM_SZ)
#define MMA_SMEM (2*BUF_SZ*2)     // 81920 bytes -> 2 CTAs/SM

__global__ void __launch_bounds__(256,2) mma_big_k(
    const __nv_bfloat16* __restrict__ Abf,
    const __nv_bfloat16* __restrict__ Bbf,
    float* __restrict__ part)
{
    extern __shared__ __nv_bfloat16 sm[];
    uint32_t smb;
    asm("{ .reg .u64 t; cvta.to.shared.u64 t, %1; cvt.u32.u64 %0, t; }" : "=r"(smb) : "l"(sm));
    const int tid = threadIdx.x;
    const int lane = tid & 31, wid = tid >> 5;
    const int grp = lane >> 2, qid = lane & 3;
    const int warp_m = (wid & 3) * 32;
    const int warp_n = (wid >> 2) * 64;
    const int n0 = blockIdx.x * 128;
    const int m0 = blockIdx.y * 128;
    const int kbeg = blockIdx.z * 1024;

    const int r0 = tid >> 2,         c8 = (tid & 3) << 3;
    const int r1 = (256 + tid) >> 2;

    float acc[2][8][4];
#pragma unroll
    for (int i=0;i<2;++i)
#pragma unroll
        for (int j=0;j<8;++j)
#pragma unroll
            for (int q=0;q<4;++q) acc[i][j][q] = 0.f;

    auto prefetch = [&](int iter, int buf){
        int k0 = kbeg + iter*32;
        uint32_t base = smb + (uint32_t)(buf*BUF_SZ)*2;
#pragma unroll
        for (int t=0; t<2; ++t){
            const __nv_bfloat16* ga0 = Abf + (size_t)t*16777216ull + (size_t)(m0+r0)*4096 + k0 + c8;
            const __nv_bfloat16* ga1 = Abf + (size_t)t*16777216ull + (size_t)(m0+r1)*4096 + k0 + c8;
            uint32_t da0 = base + (uint32_t)(t*TERM_SZ + r0*SM_ROW + c8)*2;
            uint32_t da1 = base + (uint32_t)(t*TERM_SZ + r1*SM_ROW + c8)*2;
            asm volatile("cp.async.cg.shared.global [%0], [%1], 16;" :: "r"(da0), "l"(ga0));
            asm volatile("cp.async.cg.shared.global [%0], [%1], 16;" :: "r"(da1), "l"(ga1));
            const __nv_bfloat16* gb0 = Bbf + (size_t)t*1048576ull + (size_t)(n0+r0)*4096 + k0 + c8;
            const __nv_bfloat16* gb1 = Bbf + (size_t)t*1048576ull + (size_t)(n0+r1)*4096 + k0 + c8;
            uint32_t db0 = base + (uint32_t)((2+t)*TERM_SZ + r0*SM_ROW + c8)*2;
            uint32_t db1 = base + (uint32_t)((2+t)*TERM_SZ + r1*SM_ROW + c8)*2;
            asm volatile("cp.async.cg.shared.global [%0], [%1], 16;" :: "r"(db0), "l"(gb0));
            asm volatile("cp.async.cg.shared.global [%0], [%1], 16;" :: "r"(db1), "l"(gb1));
        }
        asm volatile("cp.async.commit_group;");
    };

    prefetch(0, 0);

    for (int it = 0; it < 32; ++it){
        if (it + 1 < 32){
            prefetch(it+1, (it+1)&1);
            asm volatile("cp.async.wait_group 1;");
        } else {
            asm volatile("cp.async.wait_group 0;");
        }
        __syncthreads();
        const __nv_bfloat16* As = sm + (it&1)*BUF_SZ;
        const __nv_bfloat16* Bs = As + 2*TERM_SZ;
#pragma unroll
        for (int kk=0; kk<32; kk+=16){
            uint32_t afr[2][2][4];
#pragma unroll
            for (int t=0; t<2; ++t)
#pragma unroll
                for (int mf=0; mf<2; ++mf){
                    const __nv_bfloat16* ap = As + t*TERM_SZ + (warp_m + mf*16 + grp)*SM_ROW + kk + qid*2;
                    afr[t][mf][0] = *(const uint32_t*)(ap);
                    afr[t][mf][1] = *(const uint32_t*)(ap + 8*SM_ROW);
                    afr[t][mf][2] = *(const uint32_t*)(ap + 8);
                    afr[t][mf][3] = *(const uint32_t*)(ap + 8*SM_ROW + 8);
                }
#pragma unroll
            for (int nf=0; nf<8; ++nf){
                const __nv_bfloat16* bb = Bs + (warp_n + nf*8 + grp)*SM_ROW + kk + qid*2;
                uint32_t b0[2], b1[2];
#pragma unroll
                for (int t=0; t<2; ++t){
                    b0[t] = *(const uint32_t*)(bb + t*TERM_SZ);
                    b1[t] = *(const uint32_t*)(bb + t*TERM_SZ + 8);
                }
                mma16816(acc[0][nf], afr[0][0], b0[0], b1[0]);
                mma16816(acc[1][nf], afr[0][1], b0[0], b1[0]);
                mma16816(acc[0][nf], afr[0][0], b0[1], b1[1]);
                mma16816(acc[1][nf], afr[0][1], b0[1], b1[1]);
                mma16816(acc[0][nf], afr[1][0], b0[0], b1[0]);
                mma16816(acc[1][nf], afr[1][1], b0[0], b1[0]);
            }
        }
        __syncthreads();
    }

    float* pb = part + (size_t)blockIdx.z * (4000*256);
#pragma unroll
    for (int mf=0; mf<2; ++mf){
        int gm0 = m0 + warp_m + mf*16 + grp;
        int gm1 = gm0 + 8;
#pragma unroll
        for (int nf=0; nf<8; ++nf){
            int gn = n0 + warp_n + nf*8 + qid*2;
            if (gm0 < 4000){
                float2 v0 = make_float2(acc[mf][nf][0], acc[mf][nf][1]);
                *(float2*)(pb + (size_t)gm0*256 + gn) = v0;
            }
            if (gm1 < 4000){
                float2 v1 = make_float2(acc[mf][nf][2], acc[mf][nf][3]);
                *(float2*)(pb + (size_t)gm1*256 + gn) = v1;
            }
        }
    }
}

// ======== NT GEMM 2000x2000x256: 3-term/6-product (unchanged) ========
#define NT_BUF  (6*TERM_SZ)
#define NT_SMEM (NT_BUF*2)

template<int ACT>
__global__ void __launch_bounds__(256,2) mma_nt_k(
    const __nv_bfloat16* __restrict__ A,
    const __nv_bfloat16* __restrict__ B,
    float* __restrict__ out,
    const float* __restrict__ xsq, const float* __restrict__ ysq,
    float* __restrict__ gmax)
{
    extern __shared__ __nv_bfloat16 sm[];
    uint32_t smb;
    asm("{ .reg .u64 t; cvta.to.shared.u64 t, %1; cvt.u32.u64 %0, t; }" : "=r"(smb) : "l"(sm));
    const int tid = threadIdx.x;
    const int lane = tid & 31, wid = tid >> 5;
    const int grp = lane >> 2, qid = lane & 3;
    const int warp_m = (wid & 3) * 32;
    const int warp_n = (wid >> 2) * 64;
    const int n0 = blockIdx.x * 128;
    const int m0 = blockIdx.y * 128;

    const int r0 = tid >> 2,         c8 = (tid & 3) << 3;
    const int r1 = (256 + tid) >> 2;

    float acc[2][8][4];
#pragma unroll
    for (int i=0;i<2;++i)
#pragma unroll
        for (int j=0;j<8;++j)
#pragma unroll
            for (int q=0;q<4;++q) acc[i][j][q] = 0.f;

    const int pA[6] = {0,0,1,1,0,2};
    const int pB[6] = {0,1,0,1,2,0};

    for (int it = 0; it < 8; ++it){
        int k0 = it*32;
#pragma unroll
        for (int t=0; t<3; ++t){
            const __nv_bfloat16* ga0 = A + (size_t)t*524288ull + (size_t)(m0+r0)*256 + k0 + c8;
            const __nv_bfloat16* ga1 = A + (size_t)t*524288ull + (size_t)(m0+r1)*256 + k0 + c8;
            uint32_t da0 = smb + (uint32_t)(t*TERM_SZ + r0*SM_ROW + c8)*2;
            uint32_t da1 = smb + (uint32_t)(t*TERM_SZ + r1*SM_ROW + c8)*2;
            asm volatile("cp.async.cg.shared.global [%0], [%1], 16;" :: "r"(da0), "l"(ga0));
            asm volatile("cp.async.cg.shared.global [%0], [%1], 16;" :: "r"(da1), "l"(ga1));
            const __nv_bfloat16* gb0 = B + (size_t)t*524288ull + (size_t)(n0+r0)*256 + k0 + c8;
            const __nv_bfloat16* gb1 = B + (size_t)t*524288ull + (size_t)(n0+r1)*256 + k0 + c8;
            uint32_t db0 = smb + (uint32_t)((3+t)*TERM_SZ + r0*SM_ROW + c8)*2;
            uint32_t db1 = smb + (uint32_t)((3+t)*TERM_SZ + r1*SM_ROW + c8)*2;
            asm volatile("cp.async.cg.shared.global [%0], [%1], 16;" :: "r"(db0), "l"(gb0));
            asm volatile("cp.async.cg.shared.global [%0], [%1], 16;" :: "r"(db1), "l"(gb1));
        }
        asm volatile("cp.async.commit_group;");
        asm volatile("cp.async.wait_group 0;");
        __syncthreads();
        const __nv_bfloat16* As = sm;
        const __nv_bfloat16* Bs = sm + 3*TERM_SZ;
#pragma unroll
        for (int kk=0; kk<32; kk+=16){
            uint32_t afr[3][2][4];
#pragma unroll
            for (int t=0; t<3; ++t)
#pragma unroll
                for (int mf=0; mf<2; ++mf){
                    const __nv_bfloat16* ap = As + t*TERM_SZ + (warp_m + mf*16 + grp)*SM_ROW + kk + qid*2;
                    afr[t][mf][0] = *(const uint32_t*)(ap);
                    afr[t][mf][1] = *(const uint32_t*)(ap + 8*SM_ROW);
                    afr[t][mf][2] = *(const uint32_t*)(ap + 8);
                    afr[t][mf][3] = *(const uint32_t*)(ap + 8*SM_ROW + 8);
                }
#pragma unroll
            for (int nf=0; nf<8; ++nf){
                const __nv_bfloat16* bb = Bs + (warp_n + nf*8 + grp)*SM_ROW + kk + qid*2;
                uint32_t b0[3], b1[3];
#pragma unroll
                for (int t=0; t<3; ++t){
                    b0[t] = *(const uint32_t*)(bb + t*TERM_SZ);
                    b1[t] = *(const uint32_t*)(bb + t*TERM_SZ + 8);
                }
#pragma unroll
                for (int p=0; p<6; ++p){
                    mma16816(acc[0][nf], afr[pA[p]][0], b0[pB[p]], b1[pB[p]]);
                    mma16816(acc[1][nf], afr[pA[p]][1], b0[pB[p]], b1[pB[p]]);
                }
            }
        }
        __syncthreads();
    }

    float dmax = 0.f;
#pragma unroll
    for (int mf=0; mf<2; ++mf){
#pragma unroll
        for (int q2=0; q2<2; ++q2){
            int gm = m0 + warp_m + mf*16 + grp + q2*8;
            if (gm < 2000){
#pragma unroll
                for (int nf=0; nf<8; ++nf){
#pragma unroll
                    for (int e=0; e<2; ++e){
                        int gn = n0 + warp_n + nf*8 + qid*2 + e;
                        if (gn < 2000){
                            float v = acc[mf][nf][q2*2+e];
                            if (ACT==3){
                                v = sqrtf(fmaxf(xsq[gm]+ysq[gn]-2.f*v, 0.f));
                                dmax = fmaxf(dmax, v);
                            }
                            out[(size_t)gm*2000 + gn] = v;
                        }
                    }
                }
            }
        }
    }
    if (ACT==3){
        __shared__ float red[256];
        red[tid] = dmax; __syncthreads();
        for (int s=128;s;s>>=1){ if (tid<s) red[tid]=fmaxf(red[tid],red[tid+s]); __syncthreads(); }
        if (tid==0) atomicMax((int*)gmax, __float_as_int(red[0]));
    }
}

// ======== XW GEMM: axu = relu(x @ [wa|wu] + b), 4000x512x256 (unchanged R12) ========
__global__ void __launch_bounds__(256,2) mma_xw_k(
    const __nv_bfloat16* __restrict__ A,
    const __nv_bfloat16* __restrict__ B,
    const float* __restrict__ bias,
    float* __restrict__ out)
{
    extern __shared__ __nv_bfloat16 sm[];
    uint32_t smb;
    asm("{ .reg .u64 t; cvta.to.shared.u64 t, %1; cvt.u32.u64 %0, t; }" : "=r"(smb) : "l"(sm));
    const int tid = threadIdx.x;
    const int lane = tid & 31, wid = tid >> 5;
    const int grp = lane >> 2, qid = lane & 3;
    const int warp_m = (wid & 3) * 32;
    const int warp_n = (wid >> 2) * 64;
    const int n0 = blockIdx.x * 128;
    const int m0 = blockIdx.y * 128;

    const int r0 = tid >> 2,         c8 = (tid & 3) << 3;
    const int r1 = (256 + tid) >> 2;

    float acc[2][8][4];
#pragma unroll
    for (int i=0;i<2;++i)
#pragma unroll
        for (int j=0;j<8;++j)
#pragma unroll
            for (int q=0;q<4;++q) acc[i][j][q] = 0.f;

    const int pA[6] = {0,0,1,1,0,2};
    const int pB[6] = {0,1,0,1,2,0};

    for (int it = 0; it < 8; ++it){
        int k0 = it*32;
#pragma unroll
        for (int t=0; t<3; ++t){
            const __nv_bfloat16* ga0 = A + (size_t)t*1048576ull + (size_t)(m0+r0)*256 + k0 + c8;
            const __nv_bfloat16* ga1 = A + (size_t)t*1048576ull + (size_t)(m0+r1)*256 + k0 + c8;
            uint32_t da0 = smb + (uint32_t)(t*TERM_SZ + r0*SM_ROW + c8)*2;
            uint32_t da1 = smb + (uint32_t)(t*TERM_SZ + r1*SM_ROW + c8)*2;
            asm volatile("cp.async.cg.shared.global [%0], [%1], 16;" :: "r"(da0), "l"(ga0));
            asm volatile("cp.async.cg.shared.global [%0], [%1], 16;" :: "r"(da1), "l"(ga1));
            const __nv_bfloat16* gb0 = B + (size_t)t*131072ull + (size_t)(n0+r0)*256 + k0 + c8;
            const __nv_bfloat16* gb1 = B + (size_t)t*131072ull + (size_t)(n0+r1)*256 + k0 + c8;
            uint32_t db0 = smb + (uint32_t)((3+t)*TERM_SZ + r0*SM_ROW + c8)*2;
            uint32_t db1 = smb + (uint32_t)((3+t)*TERM_SZ + r1*SM_ROW + c8)*2;
            asm volatile("cp.async.cg.shared.global [%0], [%1], 16;" :: "r"(db0), "l"(gb0));
            asm volatile("cp.async.cg.shared.global [%0], [%1], 16;" :: "r"(db1), "l"(gb1));
        }
        asm volatile("cp.async.commit_group;");
        asm volatile("cp.async.wait_group 0;");
        __syncthreads();
        const __nv_bfloat16* As = sm;
        const __nv_bfloat16* Bs = sm + 3*TERM_SZ;
#pragma unroll
        for (int kk=0; kk<32; kk+=16){
            uint32_t afr[3][2][4];
#pragma unroll
            for (int t=0; t<3; ++t)
#pragma unroll
                for (int mf=0; mf<2; ++mf){
                    const __nv_bfloat16* ap = As + t*TERM_SZ + (warp_m + mf*16 + grp)*SM_ROW + kk + qid*2;
                    afr[t][mf][0] = *(const uint32_t*)(ap);
                    afr[t][mf][1] = *(const uint32_t*)(ap + 8*SM_ROW);
                    afr[t][mf][2] = *(const uint32_t*)(ap + 8);
                    afr[t][mf][3] = *(const uint32_t*)(ap + 8*SM_ROW + 8);
                }
#pragma unroll
            for (int nf=0; nf<8; ++nf){
                const __nv_bfloat16* bb = Bs + (warp_n + nf*8 + grp)*SM_ROW + kk + qid*2;
                uint32_t b0[3], b1[3];
#pragma unroll
                for (int t=0; t<3; ++t){
                    b0[t] = *(const uint32_t*)(bb + t*TERM_SZ);
                    b1[t] = *(const uint32_t*)(bb + t*TERM_SZ + 8);
                }
#pragma unroll
                for (int p=0; p<6; ++p){
                    mma16816(acc[0][nf], afr[pA[p]][0], b0[pB[p]], b1[pB[p]]);
                    mma16816(acc[1][nf], afr[pA[p]][1], b0[pB[p]], b1[pB[p]]);
                }
            }
        }
        __syncthreads();
    }

#pragma unroll
    for (int mf=0; mf<2; ++mf){
#pragma unroll
        for (int q2=0; q2<2; ++q2){
            int gm = m0 + warp_m + mf*16 + grp + q2*8;
            if (gm < 4000){
#pragma unroll
                for (int nf=0; nf<8; ++nf){
                    int gn = n0 + warp_n + nf*8 + qid*2;
                    float v0 = fmaxf(acc[mf][nf][q2*2+0] + bias[gn],   0.f);
                    float v1 = fmaxf(acc[mf][nf][q2*2+1] + bias[gn+1], 0.f);
                    *(float2*)(out + (size_t)gm*512 + gn) = make_float2(v0, v1);
                }
            }
        }
    }
}

// ======== cross-graph GEMM (unchanged) ========
#define CG_BUF  (4*TERM_SZ)
#define CG_SMEM (CG_BUF*2)

__global__ void __launch_bounds__(256,2) mma_cg_k(
    const __nv_bfloat16* __restrict__ A,
    const __nv_bfloat16* __restrict__ B,
    float* __restrict__ part)
{
    extern __shared__ __nv_bfloat16 sm[];
    uint32_t smb;
    asm("{ .reg .u64 t; cvta.to.shared.u64 t, %1; cvt.u32.u64 %0, t; }" : "=r"(smb) : "l"(sm));
    const int tid = threadIdx.x;
    const int lane = tid & 31, wid = tid >> 5;
    const int grp = lane >> 2, qid = lane & 3;
    const int warp_m = (wid & 3) * 32;
    const int warp_n = (wid >> 2) * 64;
    const int n0 = blockIdx.x * 128;
    const int m0 = blockIdx.y * 128;
    const int kz = blockIdx.z * 256;

    const int r0 = tid >> 2,         c8 = (tid & 3) << 3;
    const int r1 = (256 + tid) >> 2;

    float acc[2][8][4];
#pragma unroll
    for (int i=0;i<2;++i)
#pragma unroll
        for (int j=0;j<8;++j)
#pragma unroll
            for (int q=0;q<4;++q) acc[i][j][q] = 0.f;

    for (int it = 0; it < 8; ++it){
        int k0 = kz + it*32;
#pragma unroll
        for (int t=0; t<2; ++t){
            const __nv_bfloat16* ga0 = A + (size_t)t*4194304ull + (size_t)(m0+r0)*2048 + k0 + c8;
            const __nv_bfloat16* ga1 = A + (size_t)t*4194304ull + (size_t)(m0+r1)*2048 + k0 + c8;
            uint32_t da0 = smb + (uint32_t)(t*TERM_SZ + r0*SM_ROW + c8)*2;
            uint32_t da1 = smb + (uint32_t)(t*TERM_SZ + r1*SM_ROW + c8)*2;
            asm volatile("cp.async.cg.shared.global [%0], [%1], 16;" :: "r"(da0), "l"(ga0));
            asm volatile("cp.async.cg.shared.global [%0], [%1], 16;" :: "r"(da1), "l"(ga1));
            const __nv_bfloat16* gb0 = B + (size_t)t*524288ull + (size_t)(n0+r0)*2048 + k0 + c8;
            const __nv_bfloat16* gb1 = B + (size_t)t*524288ull + (size_t)(n0+r1)*2048 + k0 + c8;
            uint32_t db0 = smb + (uint32_t)((2+t)*TERM_SZ + r0*SM_ROW + c8)*2;
            uint32_t db1 = smb + (uint32_t)((2+t)*TERM_SZ + r1*SM_ROW + c8)*2;
            asm volatile("cp.async.cg.shared.global [%0], [%1], 16;" :: "r"(db0), "l"(gb0));
            asm volatile("cp.async.cg.shared.global [%0], [%1], 16;" :: "r"(db1), "l"(gb1));
        }
        asm volatile("cp.async.commit_group;");
        asm volatile("cp.async.wait_group 0;");
        __syncthreads();
        const __nv_bfloat16* As = sm;
        const __nv_bfloat16* Bs = sm + 2*TERM_SZ;
#pragma unroll
        for (int kk=0; kk<32; kk+=16){
            uint32_t afr[2][2][4];
#pragma unroll
            for (int t=0; t<2; ++t)
#pragma unroll
                for (int mf=0; mf<2; ++mf){
                    const __nv_bfloat16* ap = As + t*TERM_SZ + (warp_m + mf*16 + grp)*SM_ROW + kk + qid*2;
                    afr[t][mf][0] = *(const uint32_t*)(ap);
                    afr[t][mf][1] = *(const uint32_t*)(ap + 8*SM_ROW);
                    afr[t][mf][2] = *(const uint32_t*)(ap + 8);
                    afr[t][mf][3] = *(const uint32_t*)(ap + 8*SM_ROW + 8);
                }
#pragma unroll
            for (int nf=0; nf<8; ++nf){
                const __nv_bfloat16* bb = Bs + (warp_n + nf*8 + grp)*SM_ROW + kk + qid*2;
                uint32_t b0[2], b1[2];
#pragma unroll
                for (int t=0; t<2; ++t){
                    b0[t] = *(const uint32_t*)(bb + t*TERM_SZ);
                    b1[t] = *(const uint32_t*)(bb + t*TERM_SZ + 8);
                }
                mma16816(acc[0][nf], afr[0][0], b0[0], b1[0]);
                mma16816(acc[1][nf], afr[0][1], b0[0], b1[0]);
                mma16816(acc[0][nf], afr[0][0], b0[1], b1[1]);
                mma16816(acc[1][nf], afr[0][1], b0[1], b1[1]);
                mma16816(acc[0][nf], afr[1][0], b0[0], b1[0]);
                mma16816(acc[1][nf], afr[1][1], b0[0], b1[0]);
                mma16816(acc[0][nf], afr[1][0], b0[1], b1[1]);
                mma16816(acc[1][nf], afr[1][1], b0[1], b1[1]);
            }
        }
        __syncthreads();
    }

    float* pb = part + (size_t)blockIdx.z * (2000*256);
#pragma unroll
    for (int mf=0; mf<2; ++mf){
        int gm0 = m0 + warp_m + mf*16 + grp;
        int gm1 = gm0 + 8;
#pragma unroll
        for (int nf=0; nf<8; ++nf){
            int gn = n0 + warp_n + nf*8 + qid*2;
            if (gm0 < 2000){
                float2 v0 = make_float2(acc[mf][nf][0], acc[mf][nf][1]);
                *(float2*)(pb + (size_t)gm0*256 + gn) = v0;
            }
            if (gm1 < 2000){
                float2 v1 = make_float2(acc[mf][nf][2], acc[mf][nf][3]);
                *(float2*)(pb + (size_t)gm1*256 + gn) = v1;
            }
        }
    }
}

// --------- conversion kernels ---------
__device__ __forceinline__ void bf2split(float a, __nv_bfloat16& b0, __nv_bfloat16& b1){
    b0 = __float2bfloat16(a);
    float r1 = a - __bfloat162float(b0);
    b1 = __float2bfloat16(r1);
}
__device__ __forceinline__ void bf3split(float a, __nv_bfloat16& b0, __nv_bfloat16& b1, __nv_bfloat16& b2){
    b0 = __float2bfloat16(a);
    float r1 = a - __bfloat162float(b0);
    b1 = __float2bfloat16(r1);
    float r2 = r1 - __bfloat162float(b1);
    b2 = __float2bfloat16(r2);
}
__device__ __forceinline__ uint32_t bfpack(__nv_bfloat16 lo, __nv_bfloat16 hi){
    return (uint32_t)__bfloat16_as_ushort(lo) | ((uint32_t)__bfloat16_as_ushort(hi) << 16);
}
__global__ void convA_k(const float* __restrict__ A, __nv_bfloat16* __restrict__ out){
    size_t t = (size_t)blockIdx.x*256 + threadIdx.x;
    int r  = (int)(t >> 9);
    int k8 = (int)(t & 511) << 3;
    bool rin = (r < 4000);
    float v[8];
#pragma unroll
    for (int i=0;i<8;++i){ int k = k8 + i; v[i] = (rin && k < 4000) ? A[(size_t)r*4000 + k] : 0.f; }
    uint32_t p0[4], p1[4];
#pragma unroll
    for (int i=0;i<4;++i){
        __nv_bfloat16 a0,a1,b0,b1;
        bf2split(v[2*i],   a0,a1);
        bf2split(v[2*i+1], b0,b1);
        p0[i] = bfpack(a0,b0); p1[i] = bfpack(a1,b1);
    }
    size_t o = (size_t)r*4096 + k8;
    *(uint4*)(out + o)               = make_uint4(p0[0],p0[1],p0[2],p0[3]);
    *(uint4*)(out + o + 16777216ull) = make_uint4(p1[0],p1[1],p1[2],p1[3]);
}
__global__ void convB_k(const float* __restrict__ axu, const float* __restrict__ cs,
                        __nv_bfloat16* __restrict__ out){
    __shared__ float tile[32][33];
    int kt = blockIdx.x*32, nt = blockIdx.y*32;
    int tx = threadIdx.x, ty = threadIdx.y;
    for (int i=ty; i<32; i+=8){
        int k = kt + i;
        tile[i][tx] = (k < 4000) ? axu[(size_t)k*512 + nt + tx] * cs[k] : 0.f;
    }
    __syncthreads();
    for (int i=ty; i<32; i+=8){
        int n = nt + i, k = kt + tx;
        float a = tile[tx][i];
        __nv_bfloat16 b0,b1;
        bf2split(a, b0,b1);
        size_t o = (size_t)n*4096 + k;
        out[o] = b0; out[o + 1048576ull] = b1;
    }
}
__global__ void convNT_k(const float* __restrict__ in, __nv_bfloat16* __restrict__ out){
    int t = blockIdx.x*256 + threadIdx.x;
    int r  = t >> 5;
    int c8 = (t & 31) << 3;
    bool rin = (r < 2000);
    float v[8];
#pragma unroll
    for (int i=0;i<8;++i) v[i] = rin ? in[(size_t)r*256 + c8 + i] : 0.f;
    uint32_t p0[4], p1[4], p2[4];
#pragma unroll
    for (int i=0;i<4;++i){
        __nv_bfloat16 a0,a1,a2,b0,b1,b2;
        bf3split(v[2*i],   a0,a1,a2);
        bf3split(v[2*i+1], b0,b1,b2);
        p0[i] = bfpack(a0,b0); p1[i] = bfpack(a1,b1); p2[i] = bfpack(a2,b2);
    }
    size_t o = (size_t)r*256 + c8;
    *(uint4*)(out + o)              = make_uint4(p0[0],p0[1],p0[2],p0[3]);
    *(uint4*)(out + o + 524288ull)  = make_uint4(p1[0],p1[1],p1[2],p1[3]);
    *(uint4*)(out + o + 1048576ull) = make_uint4(p2[0],p2[1],p2[2],p2[3]);
}
// x [4000,256] -> [3][4096][256] bf16 3-term. grid 512, block 256.
__global__ void convX_k(const float* __restrict__ in, __nv_bfloat16* __restrict__ out){
    int t = blockIdx.x*256 + threadIdx.x;
    int r  = t >> 5;
    int c8 = (t & 31) << 3;
    bool rin = (r < 4000);
    float v[8];
#pragma unroll
    for (int i=0;i<8;++i) v[i] = rin ? in[(size_t)r*256 + c8 + i] : 0.f;
    uint32_t p0[4], p1[4], p2[4];
#pragma unroll
    for (int i=0;i<4;++i){
        __nv_bfloat16 a0,a1,a2,b0,b1,b2;
        bf3split(v[2*i],   a0,a1,a2);
        bf3split(v[2*i+1], b0,b1,b2);
        p0[i] = bfpack(a0,b0); p1[i] = bfpack(a1,b1); p2[i] = bfpack(a2,b2);
    }
    size_t o = (size_t)r*256 + c8;
    *(uint4*)(out + o)               = make_uint4(p0[0],p0[1],p0[2],p0[3]);
    *(uint4*)(out + o + 1048576ull)  = make_uint4(p1[0],p1[1],p1[2],p1[3]);
    *(uint4*)(out + o + 2097152ull)  = make_uint4(p2[0],p2[1],p2[2],p2[3]);
}
// [wa|wu] pack for gnn (unchanged)
__global__ void packW3_k(const float* __restrict__ wa, const float* __restrict__ wu,
                         const float* __restrict__ ba, const float* __restrict__ bu,
                         __nv_bfloat16* __restrict__ Bw, float* __restrict__ bcat){
    int n = blockIdx.x, k = threadIdx.x;
    float w = (n < 256) ? wa[(size_t)k*256 + n] : wu[(size_t)k*256 + (n-256)];
    __nv_bfloat16 b0,b1,b2;
    bf3split(w, b0,b1,b2);
    size_t o = (size_t)n*256 + k;
    Bw[o] = b0; Bw[o + 131072ull] = b1; Bw[o + 262144ull] = b2;
    if (k == 0) bcat[n] = (n < 256) ? ba[n] : bu[n-256];
}
__global__ void convS0_k(const float* __restrict__ s0, __nv_bfloat16* __restrict__ out){
    __shared__ float tile[32][33];
    int c0 = blockIdx.x*32, rb = blockIdx.y*32;
    int tx = threadIdx.x, ty = threadIdx.y;
    for (int i=ty; i<32; i+=8){
        int r = rb + i, c = c0 + tx;
        tile[i][tx] = (r < 2000 && c < 2000) ? s0[(size_t)r*2000 + c] : 0.f;
    }
    __syncthreads();
    for (int i=ty; i<32; i+=8){
        int r = rb + i, c = c0 + tx;
        float a = tile[i][tx];
        __nv_bfloat16 b0,b1;
        bf2split(a, b0,b1);
        size_t o = (size_t)r*2048 + c;
        out[o] = b0; out[o + 4194304ull] = b1;
        float at = tile[tx][i];
        __nv_bfloat16 t0,t1;
        bf2split(at, t0,t1);
        size_t ot = 8388608ull + (size_t)(c0 + i)*2048 + (rb + tx);
        out[ot] = t0; out[ot + 4194304ull] = t1;
    }
}
__global__ void convCGB_k(const float* __restrict__ x, const float* __restrict__ sc,
                          __nv_bfloat16* __restrict__ out){
    __shared__ float tile[32][33];
    int kt = blockIdx.x*32, nt = blockIdx.y*32;
    int tx = threadIdx.x, ty = threadIdx.y;
    for (int i=ty; i<32; i+=8){
        int k = kt + i;
        tile[i][tx] = (k < 2000) ? x[(size_t)k*256 + nt + tx] * sc[k] : 0.f;
    }
    __syncthreads();
    for (int i=ty; i<32; i+=8){
        int n = nt + i, k = kt + tx;
        float a = tile[tx][i];
        __nv_bfloat16 b0,b1;
        bf2split(a, b0,b1);
        size_t o = (size_t)n*2048 + k;
        out[o] = b0; out[o + 524288ull] = b1;
    }
}
// concat two [n] arrays into dst[2n]
__global__ void copy2_k(const float* __restrict__ a, const float* __restrict__ b,
                        float* __restrict__ dst, int n){
    int i = blockIdx.x*blockDim.x + threadIdx.x;
    if (i < 2*n) dst[i] = (i < n) ? a[i] : b[i - n];
}

// ---------------- generic fp32 GEMM ----------------
#define BM 128
#define BN 64
#define BK 16

template<bool TA, bool TB>
__global__ __launch_bounds__(256) void gemm_k(
    int M, int N, int K, int chunk, size_t pstride,
    const float* __restrict__ A, int lda,
    const float* __restrict__ B, int ldb,
    float* __restrict__ C, int ldc,
    const float* __restrict__ bias,
    const float* __restrict__ kscale,
    const float* __restrict__ mscale,
    const float* __restrict__ addend, int ldadd,
    int act, int accum,
    const float* __restrict__ xsq, const float* __restrict__ ysq,
    float* __restrict__ gmax)
{
    __shared__ float As[BK][BM+4];
    __shared__ float Bs[BK][BN+4];
    int tid = threadIdx.x;
    int m0 = blockIdx.y * BM;
    int n0 = blockIdx.x * BN;
    int tx = tid & 15, ty = tid >> 4;
    int ml = ty*8, nl = tx*4;

    int kbeg = blockIdx.z * chunk;
    int kend = kbeg + chunk; if (kend > K) kend = K;

    float acc[8][4];
#pragma unroll
    for (int i=0;i<8;++i)
#pragma unroll
        for (int j=0;j<4;++j) acc[i][j] = 0.f;

    for (int k0 = kbeg; k0 < kend; k0 += BK){
        if (!TA){
#pragma unroll
            for (int it=0; it<2; ++it){
                int idx = it*256 + tid;
                int row = idx >> 2;
                int kc  = (idx & 3) << 2;
                float4 vv = make_float4(0.f,0.f,0.f,0.f);
                int gm = m0 + row;
                if (gm < M) vv = *(const float4*)(A + (size_t)gm*lda + k0 + kc);
                As[kc+0][row]=vv.x; As[kc+1][row]=vv.y; As[kc+2][row]=vv.z; As[kc+3][row]=vv.w;
            }
        } else {
#pragma unroll
            for (int it=0; it<2; ++it){
                int idx = it*256 + tid;
                int kk = idx >> 5;
                int mc = (idx & 31) << 2;
                float4 vv = make_float4(0.f,0.f,0.f,0.f);
                int gm = m0 + mc;
                if (gm < M) vv = *(const float4*)(A + (size_t)(k0+kk)*lda + gm);
                *(float4*)(&As[kk][mc]) = vv;
            }
        }
        if (!TB){
            int kk = tid >> 4;
            int nc = (tid & 15) << 2;
            float4 vv = make_float4(0.f,0.f,0.f,0.f);
            int gn = n0 + nc;
            if (gn < N) vv = *(const float4*)(B + (size_t)(k0+kk)*ldb + gn);
            if (kscale){ float s = kscale[k0+kk]; vv.x*=s; vv.y*=s; vv.z*=s; vv.w*=s; }
            *(float4*)(&Bs[kk][nc]) = vv;
        } else {
            int nr = tid >> 2;
            int kc = (tid & 3) << 2;
            float4 vv = make_float4(0.f,0.f,0.f,0.f);
            int gn = n0 + nr;
            if (gn < N) vv = *(const float4*)(B + (size_t)gn*ldb + k0 + kc);
            if (kscale){
                vv.x *= kscale[k0+kc+0]; vv.y *= kscale[k0+kc+1];
                vv.z *= kscale[k0+kc+2]; vv.w *= kscale[k0+kc+3];
            }
            Bs[kc+0][nr]=vv.x; Bs[kc+1][nr]=vv.y; Bs[kc+2][nr]=vv.z; Bs[kc+3][nr]=vv.w;
        }
        __syncthreads();
#pragma unroll
        for (int kk=0; kk<BK; ++kk){
            float4 a0 = *(const float4*)(&As[kk][ml]);
            float4 a1 = *(const float4*)(&As[kk][ml+4]);
            float4 b0 = *(const float4*)(&Bs[kk][nl]);
            float av[8] = {a0.x,a0.y,a0.z,a0.w,a1.x,a1.y,a1.z,a1.w};
            float bv[4] = {b0.x,b0.y,b0.z,b0.w};
#pragma unroll
            for (int i=0;i<8;++i)
#pragma unroll
                for (int j=0;j<4;++j) acc[i][j] = fmaf(av[i], bv[j], acc[i][j]);
        }
        __syncthreads();
    }

    if (gridDim.z > 1){
        float* Cp = C + (size_t)blockIdx.z * pstride;
#pragma unroll
        for (int i=0;i<8;++i){
            int gm = m0 + ml + i;
            if (gm < M){
#pragma unroll
                for (int j=0;j<4;++j){
                    int gn = n0 + nl + j;
                    if (gn < N) Cp[(size_t)gm*ldc + gn] = acc[i][j];
                }
            }
        }
        return;
    }

    float dmax = 0.f;
#pragma unroll
    for (int i=0;i<8;++i){
        int gm = m0 + ml + i;
        if (gm < M){
#pragma unroll
            for (int j=0;j<4;++j){
                int gn = n0 + nl + j;
                if (gn < N){
                    float v = acc[i][j];
                    size_t cidx = (size_t)gm*ldc + gn;
                    if (accum)  v += C[cidx];
                    if (addend) v += addend[(size_t)gm*ldadd + gn];
                    if (bias)   v += bias[gn];
                    if (act==1)      v = fmaxf(v, 0.f);
                    else if (act==2) v = 1.f/(1.f+expf(-v));
                    else if (act==3){
                        v = sqrtf(fmaxf(xsq[gm]+ysq[gn]-2.f*v, 0.f));
                        dmax = fmaxf(dmax, v);
                    }
                    if (mscale) v *= mscale[gm];
                    C[cidx] = v;
                }
            }
        }
    }
    if (act==3){
        __shared__ float red[256];
        red[tid] = dmax; __syncthreads();
        for (int s=128;s;s>>=1){ if (tid<s) red[tid]=fmaxf(red[tid],red[tid+s]); __syncthreads(); }
        if (tid==0) atomicMax((int*)gmax, __float_as_int(red[0]));
    }
}

// ---------------- split-K reducer ----------------
__global__ void reduce_k(const float* __restrict__ part, size_t pstride, int SK,
                         const float* __restrict__ addend, int ldadd,
                         const float* __restrict__ bias,
                         const float* __restrict__ rowscale,
                         float* __restrict__ out,
                         float* __restrict__ sqout, int mode)
{
    int row = blockIdx.x, t = threadIdx.x;
    float v = 0.f;
    for (int z=0; z<SK; ++z) v += part[(size_t)z*pstride + (size_t)row*256 + t];
    if (addend) v += addend[(size_t)row*ldadd + t];
    if (bias)   v += bias[t];
    if (mode==1){
        float s = blockReduceSum256(v*v);
        v /= fmaxf(sqrtf(s), 1e-12f);
        if (sqout && t==0) sqout[row] = 1.f;
    } else if (mode==2){
        v = 1.f/(1.f+expf(-v));
        float s = blockReduceSum256(v*v);
        if (sqout && t==0) sqout[row] = s;
    }
    if (rowscale) v *= rowscale[row];
    out[(size_t)row*256 + t] = v;
}

// ---------------- elementwise / misc kernels ----------------
__global__ void zero_k(float* p, int n){
    int i = blockIdx.x*blockDim.x + threadIdx.x;
    if (i < n) p[i] = 0.f;
}
__global__ void recip_clamp_k(float* p, int n){
    int i = blockIdx.x*blockDim.x + threadIdx.x;
    if (i < n) p[i] = 1.f / fmaxf(p[i], 1e-12f);
}
__global__ void simfin_k(float* __restrict__ p, const float* __restrict__ gmax, int n){
    int i = blockIdx.x*blockDim.x + threadIdx.x;
    if (i < n){
        float inv = 1.f / gmax[0];
        p[i] = 1.f - p[i]*inv;
    }
}
__global__ void colabs_k(const float* __restrict__ A, float* __restrict__ acc){
    int j  = blockIdx.x*256 + threadIdx.x;
    int r0 = blockIdx.y*125;
    if (j >= 4000) return;
    float s = 0.f;
    for (int i=0;i<125;++i) s += fabsf(A[(size_t)(r0+i)*4000 + j]);
    atomicAdd(&acc[j], s);
}
__global__ void ssym_k(const float* __restrict__ A, float* __restrict__ S){
    int i = blockIdx.x, j = threadIdx.x;
    S[i*256+j] = 0.5f*(A[i*256+j] + A[j*256+i]);
}
__global__ void softmax_k(float* __restrict__ s0base){
    int z = blockIdx.y, row = blockIdx.x, tid = threadIdx.x;
    float* p = s0base + (size_t)z*4000000 + (size_t)row*2000;
    float a[8]; float mx = -1e30f;
#pragma unroll
    for (int i=0;i<8;++i){
        int c = tid + i*256;
        if (c < 2000){ a[i] = 200.f*p[c]; mx = fmaxf(mx, a[i]); }
        else a[i] = -1e30f;
    }
    float rowmax = blockReduceMax256(mx);
    float Mx = fmaxf(rowmax, 0.f);
    float lsum = 0.f;
#pragma unroll
    for (int i=0;i<8;++i){
        int c = tid + i*256;
        if (c < 2000){ a[i] = expf(a[i]-Mx); lsum += a[i]; }
    }
    float tot = blockReduceSum256(lsum) + 2000.f*expf(-Mx);
    float inv = 1.f/tot;
#pragma unroll
    for (int i=0;i<8;++i){
        int c = tid + i*256;
        if (c < 2000) p[c] = a[i]*inv + 1e-4f;
    }
}
__global__ void sink_col_k(const float* __restrict__ s0base, const float* __restrict__ vraw,
                           float* __restrict__ uraw, int first){
    int z = blockIdx.z;
    const float* s0 = s0base + (size_t)z*4000000;
    __shared__ float Rs[125];
    int r0 = blockIdx.y*125;
    if (threadIdx.x < 125)
        Rs[threadIdx.x] = first ? 1.f : 1.f/vraw[z*2048 + r0 + threadIdx.x];
    __syncthreads();
    int j = blockIdx.x*256 + threadIdx.x;
    if (j < 2000){
        float s = 0.f;
        for (int i=0;i<125;++i) s += s0[(size_t)(r0+i)*2000 + j]*Rs[i];
        atomicAdd(&uraw[z*2048 + j], s);
    }
}
__global__ void sink_row_k(const float* __restrict__ s0base, const float* __restrict__ uraw,
                           float* __restrict__ vraw){
    int z = blockIdx.y;
    const float* s0 = s0base + (size_t)z*4000000;
    __shared__ float Cs[2000];
    for (int i=threadIdx.x; i<2000; i+=256) Cs[i] = 1.f/uraw[z*2048 + i];
    __syncthreads();
    int w = threadIdx.x>>5, lane = threadIdx.x&31;
    int row = blockIdx.x*8 + w;
    const float* pr = s0 + (size_t)row*2000;
    float s = 0.f;
    for (int j=lane; j<2000; j+=32) s += pr[j]*Cs[j];
#pragma unroll
    for (int o=16;o;o>>=1) s += __shfl_down_sync(0xffffffffu, s, o);
    if (lane==0) vraw[z*2048 + row] = s;
}
__global__ void scales_k(const float* __restrict__ uraw, const float* __restrict__ vraw,
                         float* __restrict__ Cf, float* __restrict__ Rf){
    int z = blockIdx.y;
    int i = blockIdx.x*256 + threadIdx.x;
    if (i < 2000){
        Cf[z*2048+i] = 1.f/uraw[z*2048+i];
        Rf[z*2048+i] = 1.f/vraw[z*2048+i];
    }
}
__global__ void write_s_k(float* __restrict__ out, const float* __restrict__ s0base,
                          const float* __restrict__ Rf, const float* __restrict__ Cf){
    int row = blockIdx.y;
    int col = blockIdx.x*256 + threadIdx.x;
    if (col >= 4000) return;
    float v = 0.f;
    if (row < 2000 && col < 2000)
        v = s0base[(size_t)row*2000 + col] * Rf[row] * Cf[col];
    else if (row >= 2000 && col >= 2000)
        v = s0base[4000000 + (size_t)(row-2000)*2000 + (col-2000)]
            * Rf[2048 + row-2000] * Cf[2048 + col-2000];
    out[(size_t)row*4000 + col] = v;
}

// ---------------- host-side GEMM dispatch ----------------
static void run_gemm(int ta, int tb, int M, int N, int K,
                     const float* A, int lda, const float* B, int ldb,
                     float* C, int ldc,
                     const float* bias, const float* ks, const float* ms,
                     const float* add, int ldadd, int act, int accum,
                     const float* xsq, const float* ysq, float* gmax)
{
    dim3 grid((N+BN-1)/BN, (M+BM-1)/BM, 1);
    if (!ta && !tb)      gemm_k<false,false><<<grid,256>>>(M,N,K,K,0,A,lda,B,ldb,C,ldc,bias,ks,ms,add,ldadd,act,accum,xsq,ysq,gmax);
    else if (!ta && tb)  gemm_k<false,true ><<<grid,256>>>(M,N,K,K,0,A,lda,B,ldb,C,ldc,bias,ks,ms,add,ldadd,act,accum,xsq,ysq,gmax);
    else                 gemm_k<true ,false><<<grid,256>>>(M,N,K,K,0,A,lda,B,ldb,C,ldc,bias,ks,ms,add,ldadd,act,accum,xsq,ysq,gmax);
}
static void run_gemm_split(int ta, int M, int N, int K,
                           const float* A, int lda, const float* B, int ldb,
                           float* part, const float* ks, int SK, int chunk)
{
    dim3 grid((N+BN-1)/BN, (M+BM-1)/BM, SK);
    size_t ps = (size_t)M*N;
    if (!ta) gemm_k<false,false><<<grid,256>>>(M,N,K,chunk,ps,A,lda,B,ldb,part,N,0,ks,0,0,0,0,0,0,0,0);
    else     gemm_k<true ,false><<<grid,256>>>(M,N,K,chunk,ps,A,lda,B,ldb,part,N,0,ks,0,0,0,0,0,0,0,0);
}

extern "C" void kernel_launch(void* const* d_in, const int* in_sizes, int n_in,
                              void* d_out, int out_size)
{
    (void)in_sizes; (void)n_in; (void)out_size;
    const float* emb1      = (const float*)d_in[0];
    const float* emb2      = (const float*)d_in[1];
    const float* edge1     = (const float*)d_in[2];
    const float* edge2     = (const float*)d_in[3];
    const float* Asrc      = (const float*)d_in[4];
    const float* Atgt      = (const float*)d_in[5];
    const float* fc1n_w    = (const float*)d_in[6];
    const float* fc1n_b    = (const float*)d_in[7];
    const float* fc2n_w    = (const float*)d_in[8];
    const float* fc2n_b    = (const float*)d_in[9];
    const float* fc1e_w    = (const float*)d_in[10];
    const float* fc1e_b    = (const float*)d_in[11];
    const float* fc2e_w    = (const float*)d_in[12];
    const float* fc2e_b    = (const float*)d_in[13];
    const float* gnn_a_w   = (const float*)d_in[14];
    const float* gnn_a_b   = (const float*)d_in[15];
    const float* gnn_u_w   = (const float*)d_in[16];
    const float* gnn_u_b   = (const float*)d_in[17];
    const float* aff_A     = (const float*)d_in[18];
    const float* cg_w      = (const float*)d_in[19];
    const float* cg_b      = (const float*)d_in[20];

    float* out_s  = (float*)d_out;
    float* out_kp = out_s + 16000000;
    float* out_ke = out_s + 20000000;

    float *h,*xA1,*xB1,*xA2,*xB2,*axu,*tc1,*tc2,*s0,*T1,*Ssym,*bcat;
    float *cs,*u,*v,*Rf,*Cf,*sq,*gmax,*part;
    __nv_bfloat16 *Abf, *Bbf, *ntA, *ntB, *s0bf, *cgB, *Xbf, *Bw;
    cudaGetSymbolAddress((void**)&h,    g_h);
    cudaGetSymbolAddress((void**)&xA1,  g_xA1);
    cudaGetSymbolAddress((void**)&xB1,  g_xB1);
    cudaGetSymbolAddress((void**)&xA2,  g_xA2);
    cudaGetSymbolAddress((void**)&xB2,  g_xB2);
    cudaGetSymbolAddress((void**)&axu,  g_axu);
    cudaGetSymbolAddress((void**)&tc1,  g_tc1);
    cudaGetSymbolAddress((void**)&tc2,  g_tc2);
    cudaGetSymbolAddress((void**)&s0,   g_s0);
    cudaGetSymbolAddress((void**)&T1,   g_T1);
    cudaGetSymbolAddress((void**)&Ssym, g_Ssym);
    cudaGetSymbolAddress((void**)&bcat, g_bcat);
    cudaGetSymbolAddress((void**)&cs,   g_cs);
    cudaGetSymbolAddress((void**)&u,    g_u);
    cudaGetSymbolAddress((void**)&v,    g_v);
    cudaGetSymbolAddress((void**)&Rf,   g_Rf);
    cudaGetSymbolAddress((void**)&Cf,   g_Cf);
    cudaGetSymbolAddress((void**)&sq,   g_sq);
    cudaGetSymbolAddress((void**)&gmax, g_gmax);
    cudaGetSymbolAddress((void**)&part, g_part);
    cudaGetSymbolAddress((void**)&Abf,  g_Abf);
    cudaGetSymbolAddress((void**)&Bbf,  g_Bbf);
    cudaGetSymbolAddress((void**)&ntA,  g_ntA);
    cudaGetSymbolAddress((void**)&ntB,  g_ntB);
    cudaGetSymbolAddress((void**)&s0bf, g_s0bf);
    cudaGetSymbolAddress((void**)&cgB,  g_cgB);
    cudaGetSymbolAddress((void**)&Xbf,  g_Xbf);
    cudaGetSymbolAddress((void**)&Bw,   g_Bw);

    cudaFuncSetAttribute(mma_big_k,  cudaFuncAttributeMaxDynamicSharedMemorySize, MMA_SMEM);
    cudaFuncSetAttribute(mma_nt_k<0>, cudaFuncAttributeMaxDynamicSharedMemorySize, NT_SMEM);
    cudaFuncSetAttribute(mma_nt_k<3>, cudaFuncAttributeMaxDynamicSharedMemorySize, NT_SMEM);
    cudaFuncSetAttribute(mma_cg_k,   cudaFuncAttributeMaxDynamicSharedMemorySize, CG_SMEM);
    cudaFuncSetAttribute(mma_xw_k,   cudaFuncAttributeMaxDynamicSharedMemorySize, NT_SMEM);

    float* cur[2] = {xA1, xA2};
    float* alt[2] = {xB1, xB2};

    // ---------- A conversions (once; A is constant across layers) ----------
    convA_k<<<8192,256>>>(Asrc, Abf);
    convA_k<<<8192,256>>>(Atgt, Abf + 2ull*4096*4096);

    // ---------- Stage A: batched node/edge embedding MLPs (M=4000 per type) ----------
    // nodes: cat = [emb1; emb2]  (g_T1 reused as 4000x128 staging)
    copy2_k<<<2000,256>>>(emb1, emb2, T1, 2000*128);
    run_gemm(0,0, 4000,512,128, T1,128, fc1n_w,512, axu,512, fc1n_b,0,0,0,0,1,0,0,0,0);
    run_gemm_split(0, 4000,256,512, axu,512, fc2n_w,256, part, 0, 4, 128);
    reduce_k<<<2000,256>>>(part,          4000*256, 4, 0,0, fc2n_b, 0, xA1, sq+0,    1);
    reduce_k<<<2000,256>>>(part+2000*256, 4000*256, 4, 0,0, fc2n_b, 0, xA2, sq+2048, 1);
    // edges: cat = [edge1; edge2]
    copy2_k<<<2000,256>>>(edge1, edge2, T1, 2000*128);
    run_gemm(0,0, 4000,512,128, T1,128, fc1e_w,512, axu,512, fc1e_b,0,0,0,0,1,0,0,0,0);
    run_gemm_split(0, 4000,256,512, axu,512, fc2e_w,256, part, 0, 4, 128);
    reduce_k<<<2000,256>>>(part,          4000*256, 4, 0,0, fc2e_b, 0, xA1+2000*256, sq+4096, 2);
    reduce_k<<<2000,256>>>(part+2000*256, 4000*256, 4, 0,0, fc2e_b, 0, xA2+2000*256, sq+6144, 2);

    // ---------- Kp / Ke pairwise similarity (tensor NT path) ----------
    zero_k<<<1,32>>>(gmax, 2);
    convNT_k<<<256,256>>>(cur[0], ntA);
    convNT_k<<<256,256>>>(cur[1], ntB);
    mma_nt_k<3><<<dim3(16,16),256,NT_SMEM>>>(ntA, ntB, out_kp, sq+0, sq+2048, gmax+0);
    convNT_k<<<256,256>>>(cur[0]+2000*256, ntA);
    convNT_k<<<256,256>>>(cur[1]+2000*256, ntB);
    mma_nt_k<3><<<dim3(16,16),256,NT_SMEM>>>(ntA, ntB, out_ke, sq+4096, sq+6144, gmax+1);
    simfin_k<<<(4000000+255)/256,256>>>(out_kp, gmax+0, 4000000);
    simfin_k<<<(4000000+255)/256,256>>>(out_ke, gmax+1, 4000000);

    // ---------- A column L1 sums -> reciprocal scales ----------
    zero_k<<<(8192+255)/256,256>>>(cs, 8192);
    colabs_k<<<dim3(16,32),256>>>(Asrc, cs);
    colabs_k<<<dim3(16,32),256>>>(Atgt, cs+4096);
    recip_clamp_k<<<(8192+255)/256,256>>>(cs, 8192);

    // ---------- GNN layers ----------
    for (int i=0; i<3; ++i){
        packW3_k<<<512,256>>>(gnn_a_w + (size_t)i*65536, gnn_u_w + (size_t)i*65536,
                              gnn_a_b + (size_t)i*256,   gnn_u_b + (size_t)i*256,
                              Bw, bcat);

        for (int g=0; g<2; ++g){
            convX_k<<<512,256>>>(cur[g], Xbf);
            mma_xw_k<<<dim3(4,32),256,NT_SMEM>>>(Xbf, Bw, bcat, axu);
            convB_k<<<dim3(128,8),dim3(32,8)>>>(axu, cs + g*4096, Bbf);
            mma_big_k<<<dim3(2,32,4),256,MMA_SMEM>>>(Abf + (size_t)g*2*4096*4096, Bbf, part);
            reduce_k<<<4000,256>>>(part, 4000*256, 4, axu+256,512, 0, 0, alt[g], 0, 1);
            float* t_ = cur[g]; cur[g] = alt[g]; alt[g] = t_;
        }

        if (i >= 1){
            ssym_k<<<256,256>>>(aff_A + (size_t)i*65536, Ssym);
            for (int z=0; z<2; ++z){
                size_t off = (size_t)z*2000*256;
                run_gemm_split(0, 2000,256,256, cur[0]+off,256, Ssym,256, part, 0, 2, 128);
                reduce_k<<<2000,256>>>(part, 2000*256, 2, 0,0, 0, 0, T1, 0, 0);
                convNT_k<<<256,256>>>(T1, ntA);
                convNT_k<<<256,256>>>(cur[1]+off, ntB);
                mma_nt_k<0><<<dim3(16,16),256,NT_SMEM>>>(ntA, ntB, s0 + (size_t)z*4000000, 0,0,0);
            }
            softmax_k<<<dim3(2000,2),256>>>(s0);
            for (int t=0; t<10; ++t){
                if ((t & 1) == 0){
                    zero_k<<<(4096+255)/256,256>>>(u, 4096);
                    sink_col_k<<<dim3(8,16,2),256>>>(s0, v, u, (t==0)?1:0);
                } else {
                    sink_row_k<<<dim3(250,2),256>>>(s0, u, v);
                }
            }
            scales_k<<<dim3(8,2),256>>>(u, v, Cf, Rf);

            if (i == 1){
                for (int z=0; z<2; ++z){
                    size_t off = (size_t)z*2000*256;
                    convS0_k<<<dim3(64,64),dim3(32,8)>>>(s0 + (size_t)z*4000000, s0bf);
                    convCGB_k<<<dim3(64,8),dim3(32,8)>>>(cur[1]+off, Cf+z*2048, cgB);
                    mma_cg_k<<<dim3(2,16,8),256,CG_SMEM>>>(s0bf, cgB, part);
                    reduce_k<<<2000,256>>>(part, 2000*256, 8, 0,0, 0, Rf+z*2048, tc1+off, 0, 0);
                    convCGB_k<<<dim3(64,8),dim3(32,8)>>>(cur[0]+off, Rf+z*2048, cgB);
                    mma_cg_k<<<dim3(2,16,8),256,CG_SMEM>>>(s0bf + 8388608ull, cgB, part);
                    reduce_k<<<2000,256>>>(part, 2000*256, 8, 0,0, 0, Cf+z*2048, tc2+off, 0, 0);
                }
                run_gemm(0,0, 4000,256,256, cur[0],256, cg_w,256,        alt[0],256, cg_b,0,0,0,0,0,0,0,0,0);
                run_gemm(0,0, 4000,256,256, tc1,256,    cg_w+65536,256,  alt[0],256, 0,0,0,0,0,0,1,0,0,0);
                run_gemm(0,0, 4000,256,256, cur[1],256, cg_w,256,        alt[1],256, cg_b,0,0,0,0,0,0,0,0,0);
                run_gemm(0,0, 4000,256,256, tc2,256,    cg_w+65536,256,  alt[1],256, 0,0,0,0,0,0,1,0,0,0);
                float* t0 = cur[0]; cur[0] = alt[0]; alt[0] = t0;
                float* t1 = cur[1]; cur[1] = alt[1]; alt[1] = t1;
            }
            if (i == 2){
                write_s_k<<<dim3(16,4000),256>>>(out_s, s0, Rf, Cf);
            }
        }
    }
}

// round 15
// speedup vs baseline: 1.1063x; 1.0151x over previous
#include <cuda_runtime.h>
#include <cuda_bf16.h>
#include <cstdint>
#include <math.h>

// ---------------- static scratch (allocation-free rule) ----------------
__device__ float g_h   [2000*512];
__device__ float g_xA1 [4000*256];
__device__ float g_xB1 [4000*256];
__device__ float g_xA2 [4000*256];
__device__ float g_xB2 [4000*256];
__device__ float g_axu [4000*512];
__device__ float g_tc1 [4000*256];
__device__ float g_tc2 [4000*256];
__device__ float g_s0  [2u*2000*2000];
__device__ float g_T1  [2000*256];
__device__ float g_Ssym[256*256];
__device__ float g_bcat[512];
__device__ float g_cs  [2*4096];
__device__ float g_u   [2*2048];
__device__ float g_v   [2*2048];
__device__ float g_Rf  [2*2048];
__device__ float g_Cf  [2*2048];
__device__ float g_sq  [4*2048];
__device__ float g_gmax[2];
__device__ float g_part[5u*4000*256];                 // split-K partials
__device__ __nv_bfloat16 g_Abf[2ull*2*4096*4096];     // A 2-term bf16 (both graphs, padded)
__device__ __nv_bfloat16 g_Bbf[2ull*256*4096];        // ax^T 2-term bf16 (padded)
__device__ __nv_bfloat16 g_ntA[3u*2048*256];          // NT operand A (2- or 3-term)
__device__ __nv_bfloat16 g_ntB[3u*2048*256];          // NT operand B
__device__ __nv_bfloat16 g_s0bf[2ull*2*2048*2048];    // s0 2-term, normal + transposed
__device__ __nv_bfloat16 g_cgB [2u*256*2048];         // cross-graph B 2-term transposed
__device__ __nv_bfloat16 g_Xbf [3u*4096*256];         // x 3-term (padded rows)
__device__ __nv_bfloat16 g_Bw  [3u*512*256];          // [wa|wu]^T 3-term

// ---------------- reductions ----------------
__device__ __forceinline__ float warpReduceSum(float v){
#pragma unroll
    for (int o=16;o;o>>=1) v += __shfl_xor_sync(0xffffffffu, v, o);
    return v;
}
__device__ __forceinline__ float warpReduceMax(float v){
#pragma unroll
    for (int o=16;o;o>>=1) v = fmaxf(v, __shfl_xor_sync(0xffffffffu, v, o));
    return v;
}
__device__ __forceinline__ float blockReduceSum256(float v){
    __shared__ float sm[8];
    float w = warpReduceSum(v);
    int wi = threadIdx.x>>5, ln = threadIdx.x&31;
    if (ln==0) sm[wi] = w;
    __syncthreads();
    if (wi==0){ float t = (ln<8)?sm[ln]:0.f; t = warpReduceSum(t); if (ln==0) sm[0]=t; }
    __syncthreads();
    float r = sm[0];
    __syncthreads();
    return r;
}
__device__ __forceinline__ float blockReduceMax256(float v){
    __shared__ float sm[8];
    float w = warpReduceMax(v);
    int wi = threadIdx.x>>5, ln = threadIdx.x&31;
    if (ln==0) sm[wi] = w;
    __syncthreads();
    if (wi==0){ float t = (ln<8)?sm[ln]:-1e30f; t = warpReduceMax(t); if (ln==0) sm[0]=t; }
    __syncthreads();
    float r = sm[0];
    __syncthreads();
    return r;
}

// ================= mma.sync primitive =================
__device__ __forceinline__ void mma16816(float* d, const uint32_t* a, uint32_t b0, uint32_t b1){
    asm volatile(
        "mma.sync.aligned.m16n8k16.row.col.f32.bf16.bf16.f32 "
        "{%0,%1,%2,%3}, {%4,%5,%6,%7}, {%8,%9}, {%0,%1,%2,%3};"
        : "+f"(d[0]), "+f"(d[1]), "+f"(d[2]), "+f"(d[3])
        : "r"(a[0]), "r"(a[1]), "r"(a[2]), "r"(a[3]), "r"(b0), "r"(b1));
}

#define SM_ROW 40                 // 32 k + 8 pad bf16 (80 B rows, 16B-aligned)
#define TERM_SZ (128*SM_ROW)

// ======== big GEMM: 2-term/3-product (positive operands), unchanged ========
#define BUF_SZ  (4*TERM_SZ)
#define MMA_SMEM (2*BUF_SZ*2)     // 81920 bytes -> 2 CTAs/SM

__global__ void __launch_bounds__(256,2) mma_big_k(
    const __nv_bfloat16* __restrict__ Abf,
    const __nv_bfloat16* __restrict__ Bbf,
    float* __restrict__ part)
{
    extern __shared__ __nv_bfloat16 sm[];
    uint32_t smb;
    asm("{ .reg .u64 t; cvta.to.shared.u64 t, %1; cvt.u32.u64 %0, t; }" : "=r"(smb) : "l"(sm));
    const int tid = threadIdx.x;
    const int lane = tid & 31, wid = tid >> 5;
    const int grp = lane >> 2, qid = lane & 3;
    const int warp_m = (wid & 3) * 32;
    const int warp_n = (wid >> 2) * 64;
    const int n0 = blockIdx.x * 128;
    const int m0 = blockIdx.y * 128;
    const int kbeg = blockIdx.z * 1024;

    const int r0 = tid >> 2,         c8 = (tid & 3) << 3;
    const int r1 = (256 + tid) >> 2;

    float acc[2][8][4];
#pragma unroll
    for (int i=0;i<2;++i)
#pragma unroll
        for (int j=0;j<8;++j)
#pragma unroll
            for (int q=0;q<4;++q) acc[i][j][q] = 0.f;

    auto prefetch = [&](int iter, int buf){
        int k0 = kbeg + iter*32;
        uint32_t base = smb + (uint32_t)(buf*BUF_SZ)*2;
#pragma unroll
        for (int t=0; t<2; ++t){
            const __nv_bfloat16* ga0 = Abf + (size_t)t*16777216ull + (size_t)(m0+r0)*4096 + k0 + c8;
            const __nv_bfloat16* ga1 = Abf + (size_t)t*16777216ull + (size_t)(m0+r1)*4096 + k0 + c8;
            uint32_t da0 = base + (uint32_t)(t*TERM_SZ + r0*SM_ROW + c8)*2;
            uint32_t da1 = base + (uint32_t)(t*TERM_SZ + r1*SM_ROW + c8)*2;
            asm volatile("cp.async.cg.shared.global [%0], [%1], 16;" :: "r"(da0), "l"(ga0));
            asm volatile("cp.async.cg.shared.global [%0], [%1], 16;" :: "r"(da1), "l"(ga1));
            const __nv_bfloat16* gb0 = Bbf + (size_t)t*1048576ull + (size_t)(n0+r0)*4096 + k0 + c8;
            const __nv_bfloat16* gb1 = Bbf + (size_t)t*1048576ull + (size_t)(n0+r1)*4096 + k0 + c8;
            uint32_t db0 = base + (uint32_t)((2+t)*TERM_SZ + r0*SM_ROW + c8)*2;
            uint32_t db1 = base + (uint32_t)((2+t)*TERM_SZ + r1*SM_ROW + c8)*2;
            asm volatile("cp.async.cg.shared.global [%0], [%1], 16;" :: "r"(db0), "l"(gb0));
            asm volatile("cp.async.cg.shared.global [%0], [%1], 16;" :: "r"(db1), "l"(gb1));
        }
        asm volatile("cp.async.commit_group;");
    };

    prefetch(0, 0);

    for (int it = 0; it < 32; ++it){
        if (it + 1 < 32){
            prefetch(it+1, (it+1)&1);
            asm volatile("cp.async.wait_group 1;");
        } else {
            asm volatile("cp.async.wait_group 0;");
        }
        __syncthreads();
        const __nv_bfloat16* As = sm + (it&1)*BUF_SZ;
        const __nv_bfloat16* Bs = As + 2*TERM_SZ;
#pragma unroll
        for (int kk=0; kk<32; kk+=16){
            uint32_t afr[2][2][4];
#pragma unroll
            for (int t=0; t<2; ++t)
#pragma unroll
                for (int mf=0; mf<2; ++mf){
                    const __nv_bfloat16* ap = As + t*TERM_SZ + (warp_m + mf*16 + grp)*SM_ROW + kk + qid*2;
                    afr[t][mf][0] = *(const uint32_t*)(ap);
                    afr[t][mf][1] = *(const uint32_t*)(ap + 8*SM_ROW);
                    afr[t][mf][2] = *(const uint32_t*)(ap + 8);
                    afr[t][mf][3] = *(const uint32_t*)(ap + 8*SM_ROW + 8);
                }
#pragma unroll
            for (int nf=0; nf<8; ++nf){
                const __nv_bfloat16* bb = Bs + (warp_n + nf*8 + grp)*SM_ROW + kk + qid*2;
                uint32_t b0[2], b1[2];
#pragma unroll
                for (int t=0; t<2; ++t){
                    b0[t] = *(const uint32_t*)(bb + t*TERM_SZ);
                    b1[t] = *(const uint32_t*)(bb + t*TERM_SZ + 8);
                }
                mma16816(acc[0][nf], afr[0][0], b0[0], b1[0]);
                mma16816(acc[1][nf], afr[0][1], b0[0], b1[0]);
                mma16816(acc[0][nf], afr[0][0], b0[1], b1[1]);
                mma16816(acc[1][nf], afr[0][1], b0[1], b1[1]);
                mma16816(acc[0][nf], afr[1][0], b0[0], b1[0]);
                mma16816(acc[1][nf], afr[1][1], b0[0], b1[0]);
            }
        }
        __syncthreads();
    }

    float* pb = part + (size_t)blockIdx.z * (4000*256);
#pragma unroll
    for (int mf=0; mf<2; ++mf){
        int gm0 = m0 + warp_m + mf*16 + grp;
        int gm1 = gm0 + 8;
#pragma unroll
        for (int nf=0; nf<8; ++nf){
            int gn = n0 + warp_n + nf*8 + qid*2;
            if (gm0 < 4000){
                float2 v0 = make_float2(acc[mf][nf][0], acc[mf][nf][1]);
                *(float2*)(pb + (size_t)gm0*256 + gn) = v0;
            }
            if (gm1 < 4000){
                float2 v1 = make_float2(acc[mf][nf][2], acc[mf][nf][3]);
                *(float2*)(pb + (size_t)gm1*256 + gn) = v1;
            }
        }
    }
}

// ======== NT GEMM 2000x2000x256: 3-term/6-product (affinity only, unchanged) ========
#define NT_BUF  (6*TERM_SZ)
#define NT_SMEM (NT_BUF*2)

template<int ACT>
__global__ void __launch_bounds__(256,2) mma_nt_k(
    const __nv_bfloat16* __restrict__ A,
    const __nv_bfloat16* __restrict__ B,
    float* __restrict__ out,
    const float* __restrict__ xsq, const float* __restrict__ ysq,
    float* __restrict__ gmax)
{
    extern __shared__ __nv_bfloat16 sm[];
    uint32_t smb;
    asm("{ .reg .u64 t; cvta.to.shared.u64 t, %1; cvt.u32.u64 %0, t; }" : "=r"(smb) : "l"(sm));
    const int tid = threadIdx.x;
    const int lane = tid & 31, wid = tid >> 5;
    const int grp = lane >> 2, qid = lane & 3;
    const int warp_m = (wid & 3) * 32;
    const int warp_n = (wid >> 2) * 64;
    const int n0 = blockIdx.x * 128;
    const int m0 = blockIdx.y * 128;

    const int r0 = tid >> 2,         c8 = (tid & 3) << 3;
    const int r1 = (256 + tid) >> 2;

    float acc[2][8][4];
#pragma unroll
    for (int i=0;i<2;++i)
#pragma unroll
        for (int j=0;j<8;++j)
#pragma unroll
            for (int q=0;q<4;++q) acc[i][j][q] = 0.f;

    const int pA[6] = {0,0,1,1,0,2};
    const int pB[6] = {0,1,0,1,2,0};

    for (int it = 0; it < 8; ++it){
        int k0 = it*32;
#pragma unroll
        for (int t=0; t<3; ++t){
            const __nv_bfloat16* ga0 = A + (size_t)t*524288ull + (size_t)(m0+r0)*256 + k0 + c8;
            const __nv_bfloat16* ga1 = A + (size_t)t*524288ull + (size_t)(m0+r1)*256 + k0 + c8;
            uint32_t da0 = smb + (uint32_t)(t*TERM_SZ + r0*SM_ROW + c8)*2;
            uint32_t da1 = smb + (uint32_t)(t*TERM_SZ + r1*SM_ROW + c8)*2;
            asm volatile("cp.async.cg.shared.global [%0], [%1], 16;" :: "r"(da0), "l"(ga0));
            asm volatile("cp.async.cg.shared.global [%0], [%1], 16;" :: "r"(da1), "l"(ga1));
            const __nv_bfloat16* gb0 = B + (size_t)t*524288ull + (size_t)(n0+r0)*256 + k0 + c8;
            const __nv_bfloat16* gb1 = B + (size_t)t*524288ull + (size_t)(n0+r1)*256 + k0 + c8;
            uint32_t db0 = smb + (uint32_t)((3+t)*TERM_SZ + r0*SM_ROW + c8)*2;
            uint32_t db1 = smb + (uint32_t)((3+t)*TERM_SZ + r1*SM_ROW + c8)*2;
            asm volatile("cp.async.cg.shared.global [%0], [%1], 16;" :: "r"(db0), "l"(gb0));
            asm volatile("cp.async.cg.shared.global [%0], [%1], 16;" :: "r"(db1), "l"(gb1));
        }
        asm volatile("cp.async.commit_group;");
        asm volatile("cp.async.wait_group 0;");
        __syncthreads();
        const __nv_bfloat16* As = sm;
        const __nv_bfloat16* Bs = sm + 3*TERM_SZ;
#pragma unroll
        for (int kk=0; kk<32; kk+=16){
            uint32_t afr[3][2][4];
#pragma unroll
            for (int t=0; t<3; ++t)
#pragma unroll
                for (int mf=0; mf<2; ++mf){
                    const __nv_bfloat16* ap = As + t*TERM_SZ + (warp_m + mf*16 + grp)*SM_ROW + kk + qid*2;
                    afr[t][mf][0] = *(const uint32_t*)(ap);
                    afr[t][mf][1] = *(const uint32_t*)(ap + 8*SM_ROW);
                    afr[t][mf][2] = *(const uint32_t*)(ap + 8);
                    afr[t][mf][3] = *(const uint32_t*)(ap + 8*SM_ROW + 8);
                }
#pragma unroll
            for (int nf=0; nf<8; ++nf){
                const __nv_bfloat16* bb = Bs + (warp_n + nf*8 + grp)*SM_ROW + kk + qid*2;
                uint32_t b0[3], b1[3];
#pragma unroll
                for (int t=0; t<3; ++t){
                    b0[t] = *(const uint32_t*)(bb + t*TERM_SZ);
                    b1[t] = *(const uint32_t*)(bb + t*TERM_SZ + 8);
                }
#pragma unroll
                for (int p=0; p<6; ++p){
                    mma16816(acc[0][nf], afr[pA[p]][0], b0[pB[p]], b1[pB[p]]);
                    mma16816(acc[1][nf], afr[pA[p]][1], b0[pB[p]], b1[pB[p]]);
                }
            }
        }
        __syncthreads();
    }

    float dmax = 0.f;
#pragma unroll
    for (int mf=0; mf<2; ++mf){
#pragma unroll
        for (int q2=0; q2<2; ++q2){
            int gm = m0 + warp_m + mf*16 + grp + q2*8;
            if (gm < 2000){
#pragma unroll
                for (int nf=0; nf<8; ++nf){
#pragma unroll
                    for (int e=0; e<2; ++e){
                        int gn = n0 + warp_n + nf*8 + qid*2 + e;
                        if (gn < 2000){
                            float v = acc[mf][nf][q2*2+e];
                            if (ACT==3){
                                v = sqrtf(fmaxf(xsq[gm]+ysq[gn]-2.f*v, 0.f));
                                dmax = fmaxf(dmax, v);
                            }
                            out[(size_t)gm*2000 + gn] = v;
                        }
                    }
                }
            }
        }
    }
    if (ACT==3){
        __shared__ float red[256];
        red[tid] = dmax; __syncthreads();
        for (int s=128;s;s>>=1){ if (tid<s) red[tid]=fmaxf(red[tid],red[tid+s]); __syncthreads(); }
        if (tid==0) atomicMax((int*)gmax, __float_as_int(red[0]));
    }
}

// ======== NT2 GEMM 2000x2000x256: 2-term/4-product, double-buffered (Kp/Ke) ========
// Outputs feed 1 - d/max only (no softmax amplification) -> 2^-16 error is 60x under budget.
#define NT2_BUF  (4*TERM_SZ)
#define NT2_SMEM (2*NT2_BUF*2)    // 81920 -> 2 CTAs/SM

__global__ void __launch_bounds__(256,2) mma_nt2_k(
    const __nv_bfloat16* __restrict__ A,
    const __nv_bfloat16* __restrict__ B,
    float* __restrict__ out,
    const float* __restrict__ xsq, const float* __restrict__ ysq,
    float* __restrict__ gmax)
{
    extern __shared__ __nv_bfloat16 sm[];
    uint32_t smb;
    asm("{ .reg .u64 t; cvta.to.shared.u64 t, %1; cvt.u32.u64 %0, t; }" : "=r"(smb) : "l"(sm));
    const int tid = threadIdx.x;
    const int lane = tid & 31, wid = tid >> 5;
    const int grp = lane >> 2, qid = lane & 3;
    const int warp_m = (wid & 3) * 32;
    const int warp_n = (wid >> 2) * 64;
    const int n0 = blockIdx.x * 128;
    const int m0 = blockIdx.y * 128;

    const int r0 = tid >> 2,         c8 = (tid & 3) << 3;
    const int r1 = (256 + tid) >> 2;

    float acc[2][8][4];
#pragma unroll
    for (int i=0;i<2;++i)
#pragma unroll
        for (int j=0;j<8;++j)
#pragma unroll
            for (int q=0;q<4;++q) acc[i][j][q] = 0.f;

    auto prefetch = [&](int iter, int buf){
        int k0 = iter*32;
        uint32_t base = smb + (uint32_t)(buf*NT2_BUF)*2;
#pragma unroll
        for (int t=0; t<2; ++t){
            const __nv_bfloat16* ga0 = A + (size_t)t*524288ull + (size_t)(m0+r0)*256 + k0 + c8;
            const __nv_bfloat16* ga1 = A + (size_t)t*524288ull + (size_t)(m0+r1)*256 + k0 + c8;
            uint32_t da0 = base + (uint32_t)(t*TERM_SZ + r0*SM_ROW + c8)*2;
            uint32_t da1 = base + (uint32_t)(t*TERM_SZ + r1*SM_ROW + c8)*2;
            asm volatile("cp.async.cg.shared.global [%0], [%1], 16;" :: "r"(da0), "l"(ga0));
            asm volatile("cp.async.cg.shared.global [%0], [%1], 16;" :: "r"(da1), "l"(ga1));
            const __nv_bfloat16* gb0 = B + (size_t)t*524288ull + (size_t)(n0+r0)*256 + k0 + c8;
            const __nv_bfloat16* gb1 = B + (size_t)t*524288ull + (size_t)(n0+r1)*256 + k0 + c8;
            uint32_t db0 = base + (uint32_t)((2+t)*TERM_SZ + r0*SM_ROW + c8)*2;
            uint32_t db1 = base + (uint32_t)((2+t)*TERM_SZ + r1*SM_ROW + c8)*2;
            asm volatile("cp.async.cg.shared.global [%0], [%1], 16;" :: "r"(db0), "l"(gb0));
            asm volatile("cp.async.cg.shared.global [%0], [%1], 16;" :: "r"(db1), "l"(gb1));
        }
        asm volatile("cp.async.commit_group;");
    };

    prefetch(0, 0);

    for (int it = 0; it < 8; ++it){
        if (it + 1 < 8){
            prefetch(it+1, (it+1)&1);
            asm volatile("cp.async.wait_group 1;");
        } else {
            asm volatile("cp.async.wait_group 0;");
        }
        __syncthreads();
        const __nv_bfloat16* As = sm + (it&1)*NT2_BUF;
        const __nv_bfloat16* Bs = As + 2*TERM_SZ;
#pragma unroll
        for (int kk=0; kk<32; kk+=16){
            uint32_t afr[2][2][4];
#pragma unroll
            for (int t=0; t<2; ++t)
#pragma unroll
                for (int mf=0; mf<2; ++mf){
                    const __nv_bfloat16* ap = As + t*TERM_SZ + (warp_m + mf*16 + grp)*SM_ROW + kk + qid*2;
                    afr[t][mf][0] = *(const uint32_t*)(ap);
                    afr[t][mf][1] = *(const uint32_t*)(ap + 8*SM_ROW);
                    afr[t][mf][2] = *(const uint32_t*)(ap + 8);
                    afr[t][mf][3] = *(const uint32_t*)(ap + 8*SM_ROW + 8);
                }
#pragma unroll
            for (int nf=0; nf<8; ++nf){
                const __nv_bfloat16* bb = Bs + (warp_n + nf*8 + grp)*SM_ROW + kk + qid*2;
                uint32_t b0[2], b1[2];
#pragma unroll
                for (int t=0; t<2; ++t){
                    b0[t] = *(const uint32_t*)(bb + t*TERM_SZ);
                    b1[t] = *(const uint32_t*)(bb + t*TERM_SZ + 8);
                }
                // 4 products: a0b0, a0b1, a1b0, a1b1
                mma16816(acc[0][nf], afr[0][0], b0[0], b1[0]);
                mma16816(acc[1][nf], afr[0][1], b0[0], b1[0]);
                mma16816(acc[0][nf], afr[0][0], b0[1], b1[1]);
                mma16816(acc[1][nf], afr[0][1], b0[1], b1[1]);
                mma16816(acc[0][nf], afr[1][0], b0[0], b1[0]);
                mma16816(acc[1][nf], afr[1][1], b0[0], b1[0]);
                mma16816(acc[0][nf], afr[1][0], b0[1], b1[1]);
                mma16816(acc[1][nf], afr[1][1], b0[1], b1[1]);
            }
        }
        __syncthreads();
    }

    float dmax = 0.f;
#pragma unroll
    for (int mf=0; mf<2; ++mf){
#pragma unroll
        for (int q2=0; q2<2; ++q2){
            int gm = m0 + warp_m + mf*16 + grp + q2*8;
            if (gm < 2000){
#pragma unroll
                for (int nf=0; nf<8; ++nf){
#pragma unroll
                    for (int e=0; e<2; ++e){
                        int gn = n0 + warp_n + nf*8 + qid*2 + e;
                        if (gn < 2000){
                            float v = acc[mf][nf][q2*2+e];
                            v = sqrtf(fmaxf(xsq[gm]+ysq[gn]-2.f*v, 0.f));
                            dmax = fmaxf(dmax, v);
                            out[(size_t)gm*2000 + gn] = v;
                        }
                    }
                }
            }
        }
    }
    {
        __shared__ float red[256];
        red[tid] = dmax; __syncthreads();
        for (int s=128;s;s>>=1){ if (tid<s) red[tid]=fmaxf(red[tid],red[tid+s]); __syncthreads(); }
        if (tid==0) atomicMax((int*)gmax, __float_as_int(red[0]));
    }
}

// ======== XW GEMM: axu = relu(x @ [wa|wu] + b), 4000x512x256 (unchanged) ========
__global__ void __launch_bounds__(256,2) mma_xw_k(
    const __nv_bfloat16* __restrict__ A,
    const __nv_bfloat16* __restrict__ B,
    const float* __restrict__ bias,
    float* __restrict__ out)
{
    extern __shared__ __nv_bfloat16 sm[];
    uint32_t smb;
    asm("{ .reg .u64 t; cvta.to.shared.u64 t, %1; cvt.u32.u64 %0, t; }" : "=r"(smb) : "l"(sm));
    const int tid = threadIdx.x;
    const int lane = tid & 31, wid = tid >> 5;
    const int grp = lane >> 2, qid = lane & 3;
    const int warp_m = (wid & 3) * 32;
    const int warp_n = (wid >> 2) * 64;
    const int n0 = blockIdx.x * 128;
    const int m0 = blockIdx.y * 128;

    const int r0 = tid >> 2,         c8 = (tid & 3) << 3;
    const int r1 = (256 + tid) >> 2;

    float acc[2][8][4];
#pragma unroll
    for (int i=0;i<2;++i)
#pragma unroll
        for (int j=0;j<8;++j)
#pragma unroll
            for (int q=0;q<4;++q) acc[i][j][q] = 0.f;

    const int pA[6] = {0,0,1,1,0,2};
    const int pB[6] = {0,1,0,1,2,0};

    for (int it = 0; it < 8; ++it){
        int k0 = it*32;
#pragma unroll
        for (int t=0; t<3; ++t){
            const __nv_bfloat16* ga0 = A + (size_t)t*1048576ull + (size_t)(m0+r0)*256 + k0 + c8;
            const __nv_bfloat16* ga1 = A + (size_t)t*1048576ull + (size_t)(m0+r1)*256 + k0 + c8;
            uint32_t da0 = smb + (uint32_t)(t*TERM_SZ + r0*SM_ROW + c8)*2;
            uint32_t da1 = smb + (uint32_t)(t*TERM_SZ + r1*SM_ROW + c8)*2;
            asm volatile("cp.async.cg.shared.global [%0], [%1], 16;" :: "r"(da0), "l"(ga0));
            asm volatile("cp.async.cg.shared.global [%0], [%1], 16;" :: "r"(da1), "l"(ga1));
            const __nv_bfloat16* gb0 = B + (size_t)t*131072ull + (size_t)(n0+r0)*256 + k0 + c8;
            const __nv_bfloat16* gb1 = B + (size_t)t*131072ull + (size_t)(n0+r1)*256 + k0 + c8;
            uint32_t db0 = smb + (uint32_t)((3+t)*TERM_SZ + r0*SM_ROW + c8)*2;
            uint32_t db1 = smb + (uint32_t)((3+t)*TERM_SZ + r1*SM_ROW + c8)*2;
            asm volatile("cp.async.cg.shared.global [%0], [%1], 16;" :: "r"(db0), "l"(gb0));
            asm volatile("cp.async.cg.shared.global [%0], [%1], 16;" :: "r"(db1), "l"(gb1));
        }
        asm volatile("cp.async.commit_group;");
        asm volatile("cp.async.wait_group 0;");
        __syncthreads();
        const __nv_bfloat16* As = sm;
        const __nv_bfloat16* Bs = sm + 3*TERM_SZ;
#pragma unroll
        for (int kk=0; kk<32; kk+=16){
            uint32_t afr[3][2][4];
#pragma unroll
            for (int t=0; t<3; ++t)
#pragma unroll
                for (int mf=0; mf<2; ++mf){
                    const __nv_bfloat16* ap = As + t*TERM_SZ + (warp_m + mf*16 + grp)*SM_ROW + kk + qid*2;
                    afr[t][mf][0] = *(const uint32_t*)(ap);
                    afr[t][mf][1] = *(const uint32_t*)(ap + 8*SM_ROW);
                    afr[t][mf][2] = *(const uint32_t*)(ap + 8);
                    afr[t][mf][3] = *(const uint32_t*)(ap + 8*SM_ROW + 8);
                }
#pragma unroll
            for (int nf=0; nf<8; ++nf){
                const __nv_bfloat16* bb = Bs + (warp_n + nf*8 + grp)*SM_ROW + kk + qid*2;
                uint32_t b0[3], b1[3];
#pragma unroll
                for (int t=0; t<3; ++t){
                    b0[t] = *(const uint32_t*)(bb + t*TERM_SZ);
                    b1[t] = *(const uint32_t*)(bb + t*TERM_SZ + 8);
                }
#pragma unroll
                for (int p=0; p<6; ++p){
                    mma16816(acc[0][nf], afr[pA[p]][0], b0[pB[p]], b1[pB[p]]);
                    mma16816(acc[1][nf], afr[pA[p]][1], b0[pB[p]], b1[pB[p]]);
                }
            }
        }
        __syncthreads();
    }

#pragma unroll
    for (int mf=0; mf<2; ++mf){
#pragma unroll
        for (int q2=0; q2<2; ++q2){
            int gm = m0 + warp_m + mf*16 + grp + q2*8;
            if (gm < 4000){
#pragma unroll
                for (int nf=0; nf<8; ++nf){
                    int gn = n0 + warp_n + nf*8 + qid*2;
                    float v0 = fmaxf(acc[mf][nf][q2*2+0] + bias[gn],   0.f);
                    float v1 = fmaxf(acc[mf][nf][q2*2+1] + bias[gn+1], 0.f);
                    *(float2*)(out + (size_t)gm*512 + gn) = make_float2(v0, v1);
                }
            }
        }
    }
}

// ======== cross-graph GEMM: now double-buffered (mma_big pattern) ========
#define CG_BUF  (4*TERM_SZ)
#define CG_SMEM (2*CG_BUF*2)      // 81920 -> 2 CTAs/SM

__global__ void __launch_bounds__(256,2) mma_cg_k(
    const __nv_bfloat16* __restrict__ A,
    const __nv_bfloat16* __restrict__ B,
    float* __restrict__ part)
{
    extern __shared__ __nv_bfloat16 sm[];
    uint32_t smb;
    asm("{ .reg .u64 t; cvta.to.shared.u64 t, %1; cvt.u32.u64 %0, t; }" : "=r"(smb) : "l"(sm));
    const int tid = threadIdx.x;
    const int lane = tid & 31, wid = tid >> 5;
    const int grp = lane >> 2, qid = lane & 3;
    const int warp_m = (wid & 3) * 32;
    const int warp_n = (wid >> 2) * 64;
    const int n0 = blockIdx.x * 128;
    const int m0 = blockIdx.y * 128;
    const int kz = blockIdx.z * 256;

    const int r0 = tid >> 2,         c8 = (tid & 3) << 3;
    const int r1 = (256 + tid) >> 2;

    float acc[2][8][4];
#pragma unroll
    for (int i=0;i<2;++i)
#pragma unroll
        for (int j=0;j<8;++j)
#pragma unroll
            for (int q=0;q<4;++q) acc[i][j][q] = 0.f;

    auto prefetch = [&](int iter, int buf){
        int k0 = kz + iter*32;
        uint32_t base = smb + (uint32_t)(buf*CG_BUF)*2;
#pragma unroll
        for (int t=0; t<2; ++t){
            const __nv_bfloat16* ga0 = A + (size_t)t*4194304ull + (size_t)(m0+r0)*2048 + k0 + c8;
            const __nv_bfloat16* ga1 = A + (size_t)t*4194304ull + (size_t)(m0+r1)*2048 + k0 + c8;
            uint32_t da0 = base + (uint32_t)(t*TERM_SZ + r0*SM_ROW + c8)*2;
            uint32_t da1 = base + (uint32_t)(t*TERM_SZ + r1*SM_ROW + c8)*2;
            asm volatile("cp.async.cg.shared.global [%0], [%1], 16;" :: "r"(da0), "l"(ga0));
            asm volatile("cp.async.cg.shared.global [%0], [%1], 16;" :: "r"(da1), "l"(ga1));
            const __nv_bfloat16* gb0 = B + (size_t)t*524288ull + (size_t)(n0+r0)*2048 + k0 + c8;
            const __nv_bfloat16* gb1 = B + (size_t)t*524288ull + (size_t)(n0+r1)*2048 + k0 + c8;
            uint32_t db0 = base + (uint32_t)((2+t)*TERM_SZ + r0*SM_ROW + c8)*2;
            uint32_t db1 = base + (uint32_t)((2+t)*TERM_SZ + r1*SM_ROW + c8)*2;
            asm volatile("cp.async.cg.shared.global [%0], [%1], 16;" :: "r"(db0), "l"(gb0));
            asm volatile("cp.async.cg.shared.global [%0], [%1], 16;" :: "r"(db1), "l"(gb1));
        }
        asm volatile("cp.async.commit_group;");
    };

    prefetch(0, 0);

    for (int it = 0; it < 8; ++it){
        if (it + 1 < 8){
            prefetch(it+1, (it+1)&1);
            asm volatile("cp.async.wait_group 1;");
        } else {
            asm volatile("cp.async.wait_group 0;");
        }
        __syncthreads();
        const __nv_bfloat16* As = sm + (it&1)*CG_BUF;
        const __nv_bfloat16* Bs = As + 2*TERM_SZ;
#pragma unroll
        for (int kk=0; kk<32; kk+=16){
            uint32_t afr[2][2][4];
#pragma unroll
            for (int t=0; t<2; ++t)
#pragma unroll
                for (int mf=0; mf<2; ++mf){
                    const __nv_bfloat16* ap = As + t*TERM_SZ + (warp_m + mf*16 + grp)*SM_ROW + kk + qid*2;
                    afr[t][mf][0] = *(const uint32_t*)(ap);
                    afr[t][mf][1] = *(const uint32_t*)(ap + 8*SM_ROW);
                    afr[t][mf][2] = *(const uint32_t*)(ap + 8);
                    afr[t][mf][3] = *(const uint32_t*)(ap + 8*SM_ROW + 8);
                }
#pragma unroll
            for (int nf=0; nf<8; ++nf){
                const __nv_bfloat16* bb = Bs + (warp_n + nf*8 + grp)*SM_ROW + kk + qid*2;
                uint32_t b0[2], b1[2];
#pragma unroll
                for (int t=0; t<2; ++t){
                    b0[t] = *(const uint32_t*)(bb + t*TERM_SZ);
                    b1[t] = *(const uint32_t*)(bb + t*TERM_SZ + 8);
                }
                mma16816(acc[0][nf], afr[0][0], b0[0], b1[0]);
                mma16816(acc[1][nf], afr[0][1], b0[0], b1[0]);
                mma16816(acc[0][nf], afr[0][0], b0[1], b1[1]);
                mma16816(acc[1][nf], afr[0][1], b0[1], b1[1]);
                mma16816(acc[0][nf], afr[1][0], b0[0], b1[0]);
                mma16816(acc[1][nf], afr[1][1], b0[0], b1[0]);
                mma16816(acc[0][nf], afr[1][0], b0[1], b1[1]);
                mma16816(acc[1][nf], afr[1][1], b0[1], b1[1]);
            }
        }
        __syncthreads();
    }

    float* pb = part + (size_t)blockIdx.z * (2000*256);
#pragma unroll
    for (int mf=0; mf<2; ++mf){
        int gm0 = m0 + warp_m + mf*16 + grp;
        int gm1 = gm0 + 8;
#pragma unroll
        for (int nf=0; nf<8; ++nf){
            int gn = n0 + warp_n + nf*8 + qid*2;
            if (gm0 < 2000){
                float2 v0 = make_float2(acc[mf][nf][0], acc[mf][nf][1]);
                *(float2*)(pb + (size_t)gm0*256 + gn) = v0;
            }
            if (gm1 < 2000){
                float2 v1 = make_float2(acc[mf][nf][2], acc[mf][nf][3]);
                *(float2*)(pb + (size_t)gm1*256 + gn) = v1;
            }
        }
    }
}

// --------- conversion kernels ---------
__device__ __forceinline__ void bf2split(float a, __nv_bfloat16& b0, __nv_bfloat16& b1){
    b0 = __float2bfloat16(a);
    float r1 = a - __bfloat162float(b0);
    b1 = __float2bfloat16(r1);
}
__device__ __forceinline__ void bf3split(float a, __nv_bfloat16& b0, __nv_bfloat16& b1, __nv_bfloat16& b2){
    b0 = __float2bfloat16(a);
    float r1 = a - __bfloat162float(b0);
    b1 = __float2bfloat16(r1);
    float r2 = r1 - __bfloat162float(b1);
    b2 = __float2bfloat16(r2);
}
__device__ __forceinline__ uint32_t bfpack(__nv_bfloat16 lo, __nv_bfloat16 hi){
    return (uint32_t)__bfloat16_as_ushort(lo) | ((uint32_t)__bfloat16_as_ushort(hi) << 16);
}
__global__ void convA_k(const float* __restrict__ A, __nv_bfloat16* __restrict__ out){
    size_t t = (size_t)blockIdx.x*256 + threadIdx.x;
    int r  = (int)(t >> 9);
    int k8 = (int)(t & 511) << 3;
    bool rin = (r < 4000);
    float v[8];
#pragma unroll
    for (int i=0;i<8;++i){ int k = k8 + i; v[i] = (rin && k < 4000) ? A[(size_t)r*4000 + k] : 0.f; }
    uint32_t p0[4], p1[4];
#pragma unroll
    for (int i=0;i<4;++i){
        __nv_bfloat16 a0,a1,b0,b1;
        bf2split(v[2*i],   a0,a1);
        bf2split(v[2*i+1], b0,b1);
        p0[i] = bfpack(a0,b0); p1[i] = bfpack(a1,b1);
    }
    size_t o = (size_t)r*4096 + k8;
    *(uint4*)(out + o)               = make_uint4(p0[0],p0[1],p0[2],p0[3]);
    *(uint4*)(out + o + 16777216ull) = make_uint4(p1[0],p1[1],p1[2],p1[3]);
}
__global__ void convB_k(const float* __restrict__ axu, const float* __restrict__ cs,
                        __nv_bfloat16* __restrict__ out){
    __shared__ float tile[32][33];
    int kt = blockIdx.x*32, nt = blockIdx.y*32;
    int tx = threadIdx.x, ty = threadIdx.y;
    for (int i=ty; i<32; i+=8){
        int k = kt + i;
        tile[i][tx] = (k < 4000) ? axu[(size_t)k*512 + nt + tx] * cs[k] : 0.f;
    }
    __syncthreads();
    for (int i=ty; i<32; i+=8){
        int n = nt + i, k = kt + tx;
        float a = tile[tx][i];
        __nv_bfloat16 b0,b1;
        bf2split(a, b0,b1);
        size_t o = (size_t)n*4096 + k;
        out[o] = b0; out[o + 1048576ull] = b1;
    }
}
__global__ void convNT_k(const float* __restrict__ in, __nv_bfloat16* __restrict__ out){
    int t = blockIdx.x*256 + threadIdx.x;
    int r  = t >> 5;
    int c8 = (t & 31) << 3;
    bool rin = (r < 2000);
    float v[8];
#pragma unroll
    for (int i=0;i<8;++i) v[i] = rin ? in[(size_t)r*256 + c8 + i] : 0.f;
    uint32_t p0[4], p1[4], p2[4];
#pragma unroll
    for (int i=0;i<4;++i){
        __nv_bfloat16 a0,a1,a2,b0,b1,b2;
        bf3split(v[2*i],   a0,a1,a2);
        bf3split(v[2*i+1], b0,b1,b2);
        p0[i] = bfpack(a0,b0); p1[i] = bfpack(a1,b1); p2[i] = bfpack(a2,b2);
    }
    size_t o = (size_t)r*256 + c8;
    *(uint4*)(out + o)              = make_uint4(p0[0],p0[1],p0[2],p0[3]);
    *(uint4*)(out + o + 524288ull)  = make_uint4(p1[0],p1[1],p1[2],p1[3]);
    *(uint4*)(out + o + 1048576ull) = make_uint4(p2[0],p2[1],p2[2],p2[3]);
}
// 2-term variant for Kp/Ke operands
__global__ void convNT2_k(const float* __restrict__ in, __nv_bfloat16* __restrict__ out){
    int t = blockIdx.x*256 + threadIdx.x;
    int r  = t >> 5;
    int c8 = (t & 31) << 3;
    bool rin = (r < 2000);
    float v[8];
#pragma unroll
    for (int i=0;i<8;++i) v[i] = rin ? in[(size_t)r*256 + c8 + i] : 0.f;
    uint32_t p0[4], p1[4];
#pragma unroll
    for (int i=0;i<4;++i){
        __nv_bfloat16 a0,a1,b0,b1;
        bf2split(v[2*i],   a0,a1);
        bf2split(v[2*i+1], b0,b1);
        p0[i] = bfpack(a0,b0); p1[i] = bfpack(a1,b1);
    }
    size_t o = (size_t)r*256 + c8;
    *(uint4*)(out + o)              = make_uint4(p0[0],p0[1],p0[2],p0[3]);
    *(uint4*)(out + o + 524288ull)  = make_uint4(p1[0],p1[1],p1[2],p1[3]);
}
// x [4000,256] -> [3][4096][256] bf16 3-term. grid 512, block 256.
__global__ void convX_k(const float* __restrict__ in, __nv_bfloat16* __restrict__ out){
    int t = blockIdx.x*256 + threadIdx.x;
    int r  = t >> 5;
    int c8 = (t & 31) << 3;
    bool rin = (r < 4000);
    float v[8];
#pragma unroll
    for (int i=0;i<8;++i) v[i] = rin ? in[(size_t)r*256 + c8 + i] : 0.f;
    uint32_t p0[4], p1[4], p2[4];
#pragma unroll
    for (int i=0;i<4;++i){
        __nv_bfloat16 a0,a1,a2,b0,b1,b2;
        bf3split(v[2*i],   a0,a1,a2);
        bf3split(v[2*i+1], b0,b1,b2);
        p0[i] = bfpack(a0,b0); p1[i] = bfpack(a1,b1); p2[i] = bfpack(a2,b2);
    }
    size_t o = (size_t)r*256 + c8;
    *(uint4*)(out + o)               = make_uint4(p0[0],p0[1],p0[2],p0[3]);
    *(uint4*)(out + o + 1048576ull)  = make_uint4(p1[0],p1[1],p1[2],p1[3]);
    *(uint4*)(out + o + 2097152ull)  = make_uint4(p2[0],p2[1],p2[2],p2[3]);
}
// [wa|wu] pack for gnn (unchanged)
__global__ void packW3_k(const float* __restrict__ wa, const float* __restrict__ wu,
                         const float* __restrict__ ba, const float* __restrict__ bu,
                         __nv_bfloat16* __restrict__ Bw, float* __restrict__ bcat){
    int n = blockIdx.x, k = threadIdx.x;
    float w = (n < 256) ? wa[(size_t)k*256 + n] : wu[(size_t)k*256 + (n-256)];
    __nv_bfloat16 b0,b1,b2;
    bf3split(w, b0,b1,b2);
    size_t o = (size_t)n*256 + k;
    Bw[o] = b0; Bw[o + 131072ull] = b1; Bw[o + 262144ull] = b2;
    if (k == 0) bcat[n] = (n < 256) ? ba[n] : bu[n-256];
}
__global__ void convS0_k(const float* __restrict__ s0, __nv_bfloat16* __restrict__ out){
    __shared__ float tile[32][33];
    int c0 = blockIdx.x*32, rb = blockIdx.y*32;
    int tx = threadIdx.x, ty = threadIdx.y;
    for (int i=ty; i<32; i+=8){
        int r = rb + i, c = c0 + tx;
        tile[i][tx] = (r < 2000 && c < 2000) ? s0[(size_t)r*2000 + c] : 0.f;
    }
    __syncthreads();
    for (int i=ty; i<32; i+=8){
        int r = rb + i, c = c0 + tx;
        float a = tile[i][tx];
        __nv_bfloat16 b0,b1;
        bf2split(a, b0,b1);
        size_t o = (size_t)r*2048 + c;
        out[o] = b0; out[o + 4194304ull] = b1;
        float at = tile[tx][i];
        __nv_bfloat16 t0,t1;
        bf2split(at, t0,t1);
        size_t ot = 8388608ull + (size_t)(c0 + i)*2048 + (rb + tx);
        out[ot] = t0; out[ot + 4194304ull] = t1;
    }
}
__global__ void convCGB_k(const float* __restrict__ x, const float* __restrict__ sc,
                          __nv_bfloat16* __restrict__ out){
    __shared__ float tile[32][33];
    int kt = blockIdx.x*32, nt = blockIdx.y*32;
    int tx = threadIdx.x, ty = threadIdx.y;
    for (int i=ty; i<32; i+=8){
        int k = kt + i;
        tile[i][tx] = (k < 2000) ? x[(size_t)k*256 + nt + tx] * sc[k] : 0.f;
    }
    __syncthreads();
    for (int i=ty; i<32; i+=8){
        int n = nt + i, k = kt + tx;
        float a = tile[tx][i];
        __nv_bfloat16 b0,b1;
        bf2split(a, b0,b1);
        size_t o = (size_t)n*2048 + k;
        out[o] = b0; out[o + 524288ull] = b1;
    }
}
// concat two [n] arrays into dst[2n]
__global__ void copy2_k(const float* __restrict__ a, const float* __restrict__ b,
                        float* __restrict__ dst, int n){
    int i = blockIdx.x*blockDim.x + threadIdx.x;
    if (i < 2*n) dst[i] = (i < n) ? a[i] : b[i - n];
}

// ---------------- generic fp32 GEMM ----------------
#define BM 128
#define BN 64
#define BK 16

template<bool TA, bool TB>
__global__ __launch_bounds__(256) void gemm_k(
    int M, int N, int K, int chunk, size_t pstride,
    const float* __restrict__ A, int lda,
    const float* __restrict__ B, int ldb,
    float* __restrict__ C, int ldc,
    const float* __restrict__ bias,
    const float* __restrict__ kscale,
    const float* __restrict__ mscale,
    const float* __restrict__ addend, int ldadd,
    int act, int accum,
    const float* __restrict__ xsq, const float* __restrict__ ysq,
    float* __restrict__ gmax)
{
    __shared__ float As[BK][BM+4];
    __shared__ float Bs[BK][BN+4];
    int tid = threadIdx.x;
    int m0 = blockIdx.y * BM;
    int n0 = blockIdx.x * BN;
    int tx = tid & 15, ty = tid >> 4;
    int ml = ty*8, nl = tx*4;

    int kbeg = blockIdx.z * chunk;
    int kend = kbeg + chunk; if (kend > K) kend = K;

    float acc[8][4];
#pragma unroll
    for (int i=0;i<8;++i)
#pragma unroll
        for (int j=0;j<4;++j) acc[i][j] = 0.f;

    for (int k0 = kbeg; k0 < kend; k0 += BK){
        if (!TA){
#pragma unroll
            for (int it=0; it<2; ++it){
                int idx = it*256 + tid;
                int row = idx >> 2;
                int kc  = (idx & 3) << 2;
                float4 vv = make_float4(0.f,0.f,0.f,0.f);
                int gm = m0 + row;
                if (gm < M) vv = *(const float4*)(A + (size_t)gm*lda + k0 + kc);
                As[kc+0][row]=vv.x; As[kc+1][row]=vv.y; As[kc+2][row]=vv.z; As[kc+3][row]=vv.w;
            }
        } else {
#pragma unroll
            for (int it=0; it<2; ++it){
                int idx = it*256 + tid;
                int kk = idx >> 5;
                int mc = (idx & 31) << 2;
                float4 vv = make_float4(0.f,0.f,0.f,0.f);
                int gm = m0 + mc;
                if (gm < M) vv = *(const float4*)(A + (size_t)(k0+kk)*lda + gm);
                *(float4*)(&As[kk][mc]) = vv;
            }
        }
        if (!TB){
            int kk = tid >> 4;
            int nc = (tid & 15) << 2;
            float4 vv = make_float4(0.f,0.f,0.f,0.f);
            int gn = n0 + nc;
            if (gn < N) vv = *(const float4*)(B + (size_t)(k0+kk)*ldb + gn);
            if (kscale){ float s = kscale[k0+kk]; vv.x*=s; vv.y*=s; vv.z*=s; vv.w*=s; }
            *(float4*)(&Bs[kk][nc]) = vv;
        } else {
            int nr = tid >> 2;
            int kc = (tid & 3) << 2;
            float4 vv = make_float4(0.f,0.f,0.f,0.f);
            int gn = n0 + nr;
            if (gn < N) vv = *(const float4*)(B + (size_t)gn*ldb + k0 + kc);
            if (kscale){
                vv.x *= kscale[k0+kc+0]; vv.y *= kscale[k0+kc+1];
                vv.z *= kscale[k0+kc+2]; vv.w *= kscale[k0+kc+3];
            }
            Bs[kc+0][nr]=vv.x; Bs[kc+1][nr]=vv.y; Bs[kc+2][nr]=vv.z; Bs[kc+3][nr]=vv.w;
        }
        __syncthreads();
#pragma unroll
        for (int kk=0; kk<BK; ++kk){
            float4 a0 = *(const float4*)(&As[kk][ml]);
            float4 a1 = *(const float4*)(&As[kk][ml+4]);
            float4 b0 = *(const float4*)(&Bs[kk][nl]);
            float av[8] = {a0.x,a0.y,a0.z,a0.w,a1.x,a1.y,a1.z,a1.w};
            float bv[4] = {b0.x,b0.y,b0.z,b0.w};
#pragma unroll
            for (int i=0;i<8;++i)
#pragma unroll
                for (int j=0;j<4;++j) acc[i][j] = fmaf(av[i], bv[j], acc[i][j]);
        }
        __syncthreads();
    }

    if (gridDim.z > 1){
        float* Cp = C + (size_t)blockIdx.z * pstride;
#pragma unroll
        for (int i=0;i<8;++i){
            int gm = m0 + ml + i;
            if (gm < M){
#pragma unroll
                for (int j=0;j<4;++j){
                    int gn = n0 + nl + j;
                    if (gn < N) Cp[(size_t)gm*ldc + gn] = acc[i][j];
                }
            }
        }
        return;
    }

    float dmax = 0.f;
#pragma unroll
    for (int i=0;i<8;++i){
        int gm = m0 + ml + i;
        if (gm < M){
#pragma unroll
            for (int j=0;j<4;++j){
                int gn = n0 + nl + j;
                if (gn < N){
                    float v = acc[i][j];
                    size_t cidx = (size_t)gm*ldc + gn;
                    if (accum)  v += C[cidx];
                    if (addend) v += addend[(size_t)gm*ldadd + gn];
                    if (bias)   v += bias[gn];
                    if (act==1)      v = fmaxf(v, 0.f);
                    else if (act==2) v = 1.f/(1.f+expf(-v));
                    else if (act==3){
                        v = sqrtf(fmaxf(xsq[gm]+ysq[gn]-2.f*v, 0.f));
                        dmax = fmaxf(dmax, v);
                    }
                    if (mscale) v *= mscale[gm];
                    C[cidx] = v;
                }
            }
        }
    }
    if (act==3){
        __shared__ float red[256];
        red[tid] = dmax; __syncthreads();
        for (int s=128;s;s>>=1){ if (tid<s) red[tid]=fmaxf(red[tid],red[tid+s]); __syncthreads(); }
        if (tid==0) atomicMax((int*)gmax, __float_as_int(red[0]));
    }
}

// ---------------- split-K reducer ----------------
__global__ void reduce_k(const float* __restrict__ part, size_t pstride, int SK,
                         const float* __restrict__ addend, int ldadd,
                         const float* __restrict__ bias,
                         const float* __restrict__ rowscale,
                         float* __restrict__ out,
                         float* __restrict__ sqout, int mode)
{
    int row = blockIdx.x, t = threadIdx.x;
    float v = 0.f;
    for (int z=0; z<SK; ++z) v += part[(size_t)z*pstride + (size_t)row*256 + t];
    if (addend) v += addend[(size_t)row*ldadd + t];
    if (bias)   v += bias[t];
    if (mode==1){
        float s = blockReduceSum256(v*v);
        v /= fmaxf(sqrtf(s), 1e-12f);
        if (sqout && t==0) sqout[row] = 1.f;
    } else if (mode==2){
        v = 1.f/(1.f+expf(-v));
        float s = blockReduceSum256(v*v);
        if (sqout && t==0) sqout[row] = s;
    }
    if (rowscale) v *= rowscale[row];
    out[(size_t)row*256 + t] = v;
}

// ---------------- elementwise / misc kernels ----------------
__global__ void zero_k(float* p, int n){
    int i = blockIdx.x*blockDim.x + threadIdx.x;
    if (i < n) p[i] = 0.f;
}
__global__ void recip_clamp_k(float* p, int n){
    int i = blockIdx.x*blockDim.x + threadIdx.x;
    if (i < n) p[i] = 1.f / fmaxf(p[i], 1e-12f);
}
__global__ void simfin_k(float* __restrict__ p, const float* __restrict__ gmax, int n){
    int i = blockIdx.x*blockDim.x + threadIdx.x;
    if (i < n){
        float inv = 1.f / gmax[0];
        p[i] = 1.f - p[i]*inv;
    }
}
__global__ void colabs_k(const float* __restrict__ A, float* __restrict__ acc){
    int j  = blockIdx.x*256 + threadIdx.x;
    int r0 = blockIdx.y*125;
    if (j >= 4000) return;
    float s = 0.f;
    for (int i=0;i<125;++i) s += fabsf(A[(size_t)(r0+i)*4000 + j]);
    atomicAdd(&acc[j], s);
}
__global__ void ssym_k(const float* __restrict__ A, float* __restrict__ S){
    int i = blockIdx.x, j = threadIdx.x;
    S[i*256+j] = 0.5f*(A[i*256+j] + A[j*256+i]);
}
__global__ void softmax_k(float* __restrict__ s0base){
    int z = blockIdx.y, row = blockIdx.x, tid = threadIdx.x;
    float* p = s0base + (size_t)z*4000000 + (size_t)row*2000;
    float a[8]; float mx = -1e30f;
#pragma unroll
    for (int i=0;i<8;++i){
        int c = tid + i*256;
        if (c < 2000){ a[i] = 200.f*p[c]; mx = fmaxf(mx, a[i]); }
        else a[i] = -1e30f;
    }
    float rowmax = blockReduceMax256(mx);
    float Mx = fmaxf(rowmax, 0.f);
    float lsum = 0.f;
#pragma unroll
    for (int i=0;i<8;++i){
        int c = tid + i*256;
        if (c < 2000){ a[i] = expf(a[i]-Mx); lsum += a[i]; }
    }
    float tot = blockReduceSum256(lsum) + 2000.f*expf(-Mx);
    float inv = 1.f/tot;
#pragma unroll
    for (int i=0;i<8;++i){
        int c = tid + i*256;
        if (c < 2000) p[c] = a[i]*inv + 1e-4f;
    }
}
__global__ void sink_col_k(const float* __restrict__ s0base, const float* __restrict__ vraw,
                           float* __restrict__ uraw, int first){
    int z = blockIdx.z;
    const float* s0 = s0base + (size_t)z*4000000;
    __shared__ float Rs[125];
    int r0 = blockIdx.y*125;
    if (threadIdx.x < 125)
        Rs[threadIdx.x] = first ? 1.f : 1.f/vraw[z*2048 + r0 + threadIdx.x];
    __syncthreads();
    int j = blockIdx.x*256 + threadIdx.x;
    if (j < 2000){
        float s = 0.f;
        for (int i=0;i<125;++i) s += s0[(size_t)(r0+i)*2000 + j]*Rs[i];
        atomicAdd(&uraw[z*2048 + j], s);
    }
}
__global__ void sink_row_k(const float* __restrict__ s0base, const float* __restrict__ uraw,
                           float* __restrict__ vraw){
    int z = blockIdx.y;
    const float* s0 = s0base + (size_t)z*4000000;
    __shared__ float Cs[2000];
    for (int i=threadIdx.x; i<2000; i+=256) Cs[i] = 1.f/uraw[z*2048 + i];
    __syncthreads();
    int w = threadIdx.x>>5, lane = threadIdx.x&31;
    int row = blockIdx.x*8 + w;
    const float* pr = s0 + (size_t)row*2000;
    float s = 0.f;
    for (int j=lane; j<2000; j+=32) s += pr[j]*Cs[j];
#pragma unroll
    for (int o=16;o;o>>=1) s += __shfl_down_sync(0xffffffffu, s, o);
    if (lane==0) vraw[z*2048 + row] = s;
}
__global__ void scales_k(const float* __restrict__ uraw, const float* __restrict__ vraw,
                         float* __restrict__ Cf, float* __restrict__ Rf){
    int z = blockIdx.y;
    int i = blockIdx.x*256 + threadIdx.x;
    if (i < 2000){
        Cf[z*2048+i] = 1.f/uraw[z*2048+i];
        Rf[z*2048+i] = 1.f/vraw[z*2048+i];
    }
}
__global__ void write_s_k(float* __restrict__ out, const float* __restrict__ s0base,
                          const float* __restrict__ Rf, const float* __restrict__ Cf){
    int row = blockIdx.y;
    int col = blockIdx.x*256 + threadIdx.x;
    if (col >= 4000) return;
    float v = 0.f;
    if (row < 2000 && col < 2000)
        v = s0base[(size_t)row*2000 + col] * Rf[row] * Cf[col];
    else if (row >= 2000 && col >= 2000)
        v = s0base[4000000 + (size_t)(row-2000)*2000 + (col-2000)]
            * Rf[2048 + row-2000] * Cf[2048 + col-2000];
    out[(size_t)row*4000 + col] = v;
}

// ---------------- host-side GEMM dispatch ----------------
static void run_gemm(int ta, int tb, int M, int N, int K,
                     const float* A, int lda, const float* B, int ldb,
                     float* C, int ldc,
                     const float* bias, const float* ks, const float* ms,
                     const float* add, int ldadd, int act, int accum,
                     const float* xsq, const float* ysq, float* gmax)
{
    dim3 grid((N+BN-1)/BN, (M+BM-1)/BM, 1);
    if (!ta && !tb)      gemm_k<false,false><<<grid,256>>>(M,N,K,K,0,A,lda,B,ldb,C,ldc,bias,ks,ms,add,ldadd,act,accum,xsq,ysq,gmax);
    else if (!ta && tb)  gemm_k<false,true ><<<grid,256>>>(M,N,K,K,0,A,lda,B,ldb,C,ldc,bias,ks,ms,add,ldadd,act,accum,xsq,ysq,gmax);
    else                 gemm_k<true ,false><<<grid,256>>>(M,N,K,K,0,A,lda,B,ldb,C,ldc,bias,ks,ms,add,ldadd,act,accum,xsq,ysq,gmax);
}
static void run_gemm_split(int ta, int M, int N, int K,
                           const float* A, int lda, const float* B, int ldb,
                           float* part, const float* ks, int SK, int chunk)
{
    dim3 grid((N+BN-1)/BN, (M+BM-1)/BM, SK);
    size_t ps = (size_t)M*N;
    if (!ta) gemm_k<false,false><<<grid,256>>>(M,N,K,chunk,ps,A,lda,B,ldb,part,N,0,ks,0,0,0,0,0,0,0,0);
    else     gemm_k<true ,false><<<grid,256>>>(M,N,K,chunk,ps,A,lda,B,ldb,part,N,0,ks,0,0,0,0,0,0,0,0);
}

extern "C" void kernel_launch(void* const* d_in, const int* in_sizes, int n_in,
                              void* d_out, int out_size)
{
    (void)in_sizes; (void)n_in; (void)out_size;
    const float* emb1      = (const float*)d_in[0];
    const float* emb2      = (const float*)d_in[1];
    const float* edge1     = (const float*)d_in[2];
    const float* edge2     = (const float*)d_in[3];
    const float* Asrc      = (const float*)d_in[4];
    const float* Atgt      = (const float*)d_in[5];
    const float* fc1n_w    = (const float*)d_in[6];
    const float* fc1n_b    = (const float*)d_in[7];
    const float* fc2n_w    = (const float*)d_in[8];
    const float* fc2n_b    = (const float*)d_in[9];
    const float* fc1e_w    = (const float*)d_in[10];
    const float* fc1e_b    = (const float*)d_in[11];
    const float* fc2e_w    = (const float*)d_in[12];
    const float* fc2e_b    = (const float*)d_in[13];
    const float* gnn_a_w   = (const float*)d_in[14];
    const float* gnn_a_b   = (const float*)d_in[15];
    const float* gnn_u_w   = (const float*)d_in[16];
    const float* gnn_u_b   = (const float*)d_in[17];
    const float* aff_A     = (const float*)d_in[18];
    const float* cg_w      = (const float*)d_in[19];
    const float* cg_b      = (const float*)d_in[20];

    float* out_s  = (float*)d_out;
    float* out_kp = out_s + 16000000;
    float* out_ke = out_s + 20000000;

    float *h,*xA1,*xB1,*xA2,*xB2,*axu,*tc1,*tc2,*s0,*T1,*Ssym,*bcat;
    float *cs,*u,*v,*Rf,*Cf,*sq,*gmax,*part;
    __nv_bfloat16 *Abf, *Bbf, *ntA, *ntB, *s0bf, *cgB, *Xbf, *Bw;
    cudaGetSymbolAddress((void**)&h,    g_h);
    cudaGetSymbolAddress((void**)&xA1,  g_xA1);
    cudaGetSymbolAddress((void**)&xB1,  g_xB1);
    cudaGetSymbolAddress((void**)&xA2,  g_xA2);
    cudaGetSymbolAddress((void**)&xB2,  g_xB2);
    cudaGetSymbolAddress((void**)&axu,  g_axu);
    cudaGetSymbolAddress((void**)&tc1,  g_tc1);
    cudaGetSymbolAddress((void**)&tc2,  g_tc2);
    cudaGetSymbolAddress((void**)&s0,   g_s0);
    cudaGetSymbolAddress((void**)&T1,   g_T1);
    cudaGetSymbolAddress((void**)&Ssym, g_Ssym);
    cudaGetSymbolAddress((void**)&bcat, g_bcat);
    cudaGetSymbolAddress((void**)&cs,   g_cs);
    cudaGetSymbolAddress((void**)&u,    g_u);
    cudaGetSymbolAddress((void**)&v,    g_v);
    cudaGetSymbolAddress((void**)&Rf,   g_Rf);
    cudaGetSymbolAddress((void**)&Cf,   g_Cf);
    cudaGetSymbolAddress((void**)&sq,   g_sq);
    cudaGetSymbolAddress((void**)&gmax, g_gmax);
    cudaGetSymbolAddress((void**)&part, g_part);
    cudaGetSymbolAddress((void**)&Abf,  g_Abf);
    cudaGetSymbolAddress((void**)&Bbf,  g_Bbf);
    cudaGetSymbolAddress((void**)&ntA,  g_ntA);
    cudaGetSymbolAddress((void**)&ntB,  g_ntB);
    cudaGetSymbolAddress((void**)&s0bf, g_s0bf);
    cudaGetSymbolAddress((void**)&cgB,  g_cgB);
    cudaGetSymbolAddress((void**)&Xbf,  g_Xbf);
    cudaGetSymbolAddress((void**)&Bw,   g_Bw);

    cudaFuncSetAttribute(mma_big_k,  cudaFuncAttributeMaxDynamicSharedMemorySize, MMA_SMEM);
    cudaFuncSetAttribute(mma_nt_k<0>, cudaFuncAttributeMaxDynamicSharedMemorySize, NT_SMEM);
    cudaFuncSetAttribute(mma_nt_k<3>, cudaFuncAttributeMaxDynamicSharedMemorySize, NT_SMEM);
    cudaFuncSetAttribute(mma_nt2_k,  cudaFuncAttributeMaxDynamicSharedMemorySize, NT2_SMEM);
    cudaFuncSetAttribute(mma_cg_k,   cudaFuncAttributeMaxDynamicSharedMemorySize, CG_SMEM);
    cudaFuncSetAttribute(mma_xw_k,   cudaFuncAttributeMaxDynamicSharedMemorySize, NT_SMEM);

    float* cur[2] = {xA1, xA2};
    float* alt[2] = {xB1, xB2};

    // ---------- A conversions (once; A is constant across layers) ----------
    convA_k<<<8192,256>>>(Asrc, Abf);
    convA_k<<<8192,256>>>(Atgt, Abf + 2ull*4096*4096);

    // ---------- Stage A: batched node/edge embedding MLPs (M=4000 per type) ----------
    copy2_k<<<2000,256>>>(emb1, emb2, T1, 2000*128);
    run_gemm(0,0, 4000,512,128, T1,128, fc1n_w,512, axu,512, fc1n_b,0,0,0,0,1,0,0,0,0);
    run_gemm_split(0, 4000,256,512, axu,512, fc2n_w,256, part, 0, 4, 128);
    reduce_k<<<2000,256>>>(part,          4000*256, 4, 0,0, fc2n_b, 0, xA1, sq+0,    1);
    reduce_k<<<2000,256>>>(part+2000*256, 4000*256, 4, 0,0, fc2n_b, 0, xA2, sq+2048, 1);
    copy2_k<<<2000,256>>>(edge1, edge2, T1, 2000*128);
    run_gemm(0,0, 4000,512,128, T1,128, fc1e_w,512, axu,512, fc1e_b,0,0,0,0,1,0,0,0,0);
    run_gemm_split(0, 4000,256,512, axu,512, fc2e_w,256, part, 0, 4, 128);
    reduce_k<<<2000,256>>>(part,          4000*256, 4, 0,0, fc2e_b, 0, xA1+2000*256, sq+4096, 2);
    reduce_k<<<2000,256>>>(part+2000*256, 4000*256, 4, 0,0, fc2e_b, 0, xA2+2000*256, sq+6144, 2);

    // ---------- Kp / Ke pairwise similarity (2-term tensor NT path) ----------
    zero_k<<<1,32>>>(gmax, 2);
    convNT2_k<<<256,256>>>(cur[0], ntA);
    convNT2_k<<<256,256>>>(cur[1], ntB);
    mma_nt2_k<<<dim3(16,16),256,NT2_SMEM>>>(ntA, ntB, out_kp, sq+0, sq+2048, gmax+0);
    convNT2_k<<<256,256>>>(cur[0]+2000*256, ntA);
    convNT2_k<<<256,256>>>(cur[1]+2000*256, ntB);
    mma_nt2_k<<<dim3(16,16),256,NT2_SMEM>>>(ntA, ntB, out_ke, sq+4096, sq+6144, gmax+1);
    simfin_k<<<(4000000+255)/256,256>>>(out_kp, gmax+0, 4000000);
    simfin_k<<<(4000000+255)/256,256>>>(out_ke, gmax+1, 4000000);

    // ---------- A column L1 sums -> reciprocal scales ----------
    zero_k<<<(8192+255)/256,256>>>(cs, 8192);
    colabs_k<<<dim3(16,32),256>>>(Asrc, cs);
    colabs_k<<<dim3(16,32),256>>>(Atgt, cs+4096);
    recip_clamp_k<<<(8192+255)/256,256>>>(cs, 8192);

    // ---------- GNN layers ----------
    for (int i=0; i<3; ++i){
        packW3_k<<<512,256>>>(gnn_a_w + (size_t)i*65536, gnn_u_w + (size_t)i*65536,
                              gnn_a_b + (size_t)i*256,   gnn_u_b + (size_t)i*256,
                              Bw, bcat);

        for (int g=0; g<2; ++g){
            convX_k<<<512,256>>>(cur[g], Xbf);
            mma_xw_k<<<dim3(4,32),256,NT_SMEM>>>(Xbf, Bw, bcat, axu);
            convB_k<<<dim3(128,8),dim3(32,8)>>>(axu, cs + g*4096, Bbf);
            mma_big_k<<<dim3(2,32,4),256,MMA_SMEM>>>(Abf + (size_t)g*2*4096*4096, Bbf, part);
            reduce_k<<<4000,256>>>(part, 4000*256, 4, axu+256,512, 0, 0, alt[g], 0, 1);
            float* t_ = cur[g]; cur[g] = alt[g]; alt[g] = t_;
        }

        if (i >= 1){
            ssym_k<<<256,256>>>(aff_A + (size_t)i*65536, Ssym);
            for (int z=0; z<2; ++z){
                size_t off = (size_t)z*2000*256;
                run_gemm_split(0, 2000,256,256, cur[0]+off,256, Ssym,256, part, 0, 2, 128);
                reduce_k<<<2000,256>>>(part, 2000*256, 2, 0,0, 0, 0, T1, 0, 0);
                convNT_k<<<256,256>>>(T1, ntA);
                convNT_k<<<256,256>>>(cur[1]+off, ntB);
                mma_nt_k<0><<<dim3(16,16),256,NT_SMEM>>>(ntA, ntB, s0 + (size_t)z*4000000, 0,0,0);
            }
            softmax_k<<<dim3(2000,2),256>>>(s0);
            for (int t=0; t<10; ++t){
                if ((t & 1) == 0){
                    zero_k<<<(4096+255)/256,256>>>(u, 4096);
                    sink_col_k<<<dim3(8,16,2),256>>>(s0, v, u, (t==0)?1:0);
                } else {
                    sink_row_k<<<dim3(250,2),256>>>(s0, u, v);
                }
            }
            scales_k<<<dim3(8,2),256>>>(u, v, Cf, Rf);

            if (i == 1){
                for (int z=0; z<2; ++z){
                    size_t off = (size_t)z*2000*256;
                    convS0_k<<<dim3(64,64),dim3(32,8)>>>(s0 + (size_t)z*4000000, s0bf);
                    convCGB_k<<<dim3(64,8),dim3(32,8)>>>(cur[1]+off, Cf+z*2048, cgB);
                    mma_cg_k<<<dim3(2,16,8),256,CG_SMEM>>>(s0bf, cgB, part);
                    reduce_k<<<2000,256>>>(part, 2000*256, 8, 0,0, 0, Rf+z*2048, tc1+off, 0, 0);
                    convCGB_k<<<dim3(64,8),dim3(32,8)>>>(cur[0]+off, Rf+z*2048, cgB);
                    mma_cg_k<<<dim3(2,16,8),256,CG_SMEM>>>(s0bf + 8388608ull, cgB, part);
                    reduce_k<<<2000,256>>>(part, 2000*256, 8, 0,0, 0, Cf+z*2048, tc2+off, 0, 0);
                }
                run_gemm(0,0, 4000,256,256, cur[0],256, cg_w,256,        alt[0],256, cg_b,0,0,0,0,0,0,0,0,0);
                run_gemm(0,0, 4000,256,256, tc1,256,    cg_w+65536,256,  alt[0],256, 0,0,0,0,0,0,1,0,0,0);
                run_gemm(0,0, 4000,256,256, cur[1],256, cg_w,256,        alt[1],256, cg_b,0,0,0,0,0,0,0,0,0);
                run_gemm(0,0, 4000,256,256, tc2,256,    cg_w+65536,256,  alt[1],256, 0,0,0,0,0,0,1,0,0,0);
                float* t0 = cur[0]; cur[0] = alt[0]; alt[0] = t0;
                float* t1 = cur[1]; cur[1] = alt[1]; alt[1] = t1;
            }
            if (i == 2){
                write_s_k<<<dim3(16,4000),256>>>(out_s, s0, Rf, Cf);
            }
        }
    }
}